// round 15
// baseline (speedup 1.0000x reference)
#include <cuda_runtime.h>
#include <cuda_bf16.h>
#include <math.h>
#include <stdint.h>

// ---------------- problem constants ----------------
#define BB 8
#define TPRE 6144
#define CIN 8
#define OUTLEN 2048
#define OUTC 8
#define AUXD 16
#define DM 256
#define DSTATE 32
#define HD 64
#define DIN 512
#define NH 8
#define CONVDIM 576
#define DPROJ 1096
#define NPADI 1152
#define PATCHN 16
#define NTOK 512
#define NMASK 384
#define TFWD 512
#define TBWD 128
#define MFWD (BB*TFWD)    // 4096
#define MBWD (BB*TBWD)    // 1024
#define MTOT (MFWD+MBWD)  // 5120
#define MPATCH (BB*NMASK) // 3072
#define KPATCH 4096
#define KSPLIT 2
#define KCHUNK 2048

// ---------------- scratch ----------------
__device__ __align__(256) float g_aux[BB*DM];
__device__ __align__(256) float g_pp[(size_t)KSPLIT*MPATCH*DM];
__device__ __align__(256) float g_hf[(size_t)BB*NTOK*DM];
__device__ __align__(256) float g_hb[(size_t)BB*TBWD*DM];
__device__ __align__(256) float g_zx[(size_t)MTOT*DPROJ];
__device__ __align__(256) float g_x [(size_t)MTOT*DIN];
__device__ __align__(256) float g_Bb[(size_t)MTOT*DSTATE];
__device__ __align__(256) float g_Cb[(size_t)MTOT*DSTATE];
__device__ __align__(256) float g_dt[(size_t)MTOT*NH];
__device__ __align__(256) float g_y [(size_t)MTOT*DIN];

__device__ __align__(256) __nv_bfloat16 g_pch[(size_t)MPATCH*KPATCH];
__device__ __align__(256) __nv_bfloat16 g_pcl[(size_t)MPATCH*KPATCH];
__device__ __align__(256) __nv_bfloat16 g_uh[(size_t)MTOT*DM];
__device__ __align__(256) __nv_bfloat16 g_ul[(size_t)MTOT*DM];
__device__ __align__(256) __nv_bfloat16 g_u2h[(size_t)MTOT*DIN];
__device__ __align__(256) __nv_bfloat16 g_u2l[(size_t)MTOT*DIN];
__device__ __align__(256) __nv_bfloat16 g_wph[(size_t)DM*KPATCH];
__device__ __align__(256) __nv_bfloat16 g_wpl[(size_t)DM*KPATCH];
__device__ __align__(256) __nv_bfloat16 g_wih[(size_t)4*NPADI*DM];
__device__ __align__(256) __nv_bfloat16 g_wil[(size_t)4*NPADI*DM];
__device__ __align__(256) __nv_bfloat16 g_woh[(size_t)4*DM*DIN];
__device__ __align__(256) __nv_bfloat16 g_wol[(size_t)4*DM*DIN];
__device__ __align__(256) __nv_bfloat16 g_wfh[(size_t)128*2*DM];
__device__ __align__(256) __nv_bfloat16 g_wfl[(size_t)128*2*DM];

__device__ __forceinline__ float silu_f(float v) { return v / (1.0f + expf(-v)); }
__device__ __forceinline__ float softplus_f(float v) { return (v > 20.0f) ? v : log1pf(expf(v)); }

__device__ __forceinline__ void split_bf16(float a, __nv_bfloat16* h, __nv_bfloat16* l) {
    __nv_bfloat16 hh = __float2bfloat16_rn(a);
    *h = hh;
    *l = __float2bfloat16_rn(a - __bfloat162float(hh));
}

// ---------------- baseline-PTX helpers ----------------
__device__ __forceinline__ uint32_t smem_u32(const void* p) {
    uint32_t a;
    asm("{ .reg .u64 t; cvta.to.shared.u64 t, %1; cvt.u32.u64 %0, t; }" : "=r"(a) : "l"(p));
    return a;
}
__device__ __forceinline__ void cp_async16(uint32_t dst, const void* src) {
    asm volatile("cp.async.cg.shared.global [%0], [%1], 16;" :: "r"(dst), "l"(src));
}
#define CP_COMMIT() asm volatile("cp.async.commit_group;" ::: "memory")
#define CP_WAIT0()  asm volatile("cp.async.wait_group 0;" ::: "memory")

__device__ __forceinline__ void ldsm_x4(uint32_t* r, uint32_t addr) {
    asm volatile("ldmatrix.sync.aligned.m8n8.x4.shared.b16 {%0,%1,%2,%3}, [%4];"
                 : "=r"(r[0]), "=r"(r[1]), "=r"(r[2]), "=r"(r[3]) : "r"(addr));
}
__device__ __forceinline__ void mma_bf16(float* d, const uint32_t* a, uint32_t b0, uint32_t b1) {
    asm volatile("mma.sync.aligned.m16n8k16.row.col.f32.bf16.bf16.f32 "
        "{%0,%1,%2,%3}, {%4,%5,%6,%7}, {%8,%9}, {%0,%1,%2,%3};"
        : "+f"(d[0]), "+f"(d[1]), "+f"(d[2]), "+f"(d[3])
        : "r"(a[0]), "r"(a[1]), "r"(a[2]), "r"(a[3]), "r"(b0), "r"(b1));
}

#define PADB 80

// ---------------- aux bias ----------------
__global__ void k_aux(const float* __restrict__ y_aux, const float* __restrict__ aux_w,
                      const float* __restrict__ aux_b, float* __restrict__ out) {
    __shared__ float ys[BB*AUXD];
    int c = threadIdx.x;
    if (c < BB*AUXD) ys[c] = y_aux[c];
    __syncthreads();
    float wcol[AUXD];
#pragma unroll
    for (int i = 0; i < AUXD; i++) wcol[i] = aux_w[i*DM + c];
    float bias = aux_b[c];
    for (int b = 0; b < BB; b++) {
        float acc = bias;
#pragma unroll
        for (int i = 0; i < AUXD; i++) acc += ys[b*AUXD + i] * wcol[i];
        out[b*DM + c] = silu_f(acc);
    }
}

// ---------------- pre-conv -> bf16 hi/lo ----------------
__global__ void k_preconv(const float* __restrict__ xp, const float* __restrict__ w,
                          const float* __restrict__ bias,
                          __nv_bfloat16* __restrict__ ph, __nv_bfloat16* __restrict__ pl) {
    int m = blockIdx.x;
    int b = m / NMASK, j = m % NMASK;
    int t0 = j * PATCHN;
    __shared__ float xs[20][CIN];
    int tid = threadIdx.x;
    if (tid < 20*CIN) {
        int tt = t0 - 2 + tid / CIN;
        int i = tid % CIN;
        xs[tid/CIN][i] = (tt >= 0 && tt < TPRE) ? xp[((size_t)b*TPRE + tt)*CIN + i] : 0.0f;
    }
    __syncthreads();
    int c = tid;
    float wr[CIN*5];
#pragma unroll
    for (int q = 0; q < CIN*5; q++) wr[q] = w[c*CIN*5 + q];
    float bi = bias[c];
    size_t ob = (size_t)m*KPATCH + c*PATCHN;
#pragma unroll
    for (int k = 0; k < PATCHN; k++) {
        float acc = bi;
#pragma unroll
        for (int i = 0; i < CIN; i++)
#pragma unroll
            for (int q = 0; q < 5; q++)
                acc += xs[k+q][i] * wr[i*5 + q];
        float v = silu_f(acc);
        __nv_bfloat16 h, l; split_bf16(v, &h, &l);
        ph[ob + k] = h; pl[ob + k] = l;
    }
}

// ---------------- weight conversions ----------------
__global__ void k_cvt_patchw(const float* __restrict__ w,
                             __nv_bfloat16* __restrict__ hi, __nv_bfloat16* __restrict__ lo) {
    int i = blockIdx.x * 256 + threadIdx.x;
    float a = w[i];
    __nv_bfloat16 h, l; split_bf16(a, &h, &l);
    hi[i] = h; lo[i] = l;
}

// merged: z 0..3 inproj slots; z 4..7 outproj; z 8 final
__global__ void k_cvt_all(const float* __restrict__ fWi, const float* __restrict__ bWi,
                          const float* __restrict__ fWo, const float* __restrict__ bWo,
                          const float* __restrict__ pow_,
                          __nv_bfloat16* __restrict__ wih, __nv_bfloat16* __restrict__ wil,
                          __nv_bfloat16* __restrict__ woh, __nv_bfloat16* __restrict__ wol,
                          __nv_bfloat16* __restrict__ wfh, __nv_bfloat16* __restrict__ wfl) {
    int z = blockIdx.z;
    const float* src; int K, N, Npad; __nv_bfloat16 *dh, *dl;
    if (z < 4) {
        src = ((z >> 1) ? bWi : fWi) + (size_t)(z & 1)*DM*DPROJ;
        K = DM; N = DPROJ; Npad = NPADI;
        dh = wih + (size_t)z*NPADI*DM; dl = wil + (size_t)z*NPADI*DM;
    } else if (z < 8) {
        int s = z - 4;
        src = ((s >> 1) ? bWo : fWo) + (size_t)(s & 1)*DIN*DM;
        K = DIN; N = DM; Npad = DM;
        dh = woh + (size_t)s*DM*DIN; dl = wol + (size_t)s*DM*DIN;
    } else {
        src = pow_; K = 2*DM; N = 128; Npad = 128; dh = wfh; dl = wfl;
    }
    int i = blockIdx.x * 256 + threadIdx.x;
    if (i >= Npad*K) return;
    int n = i / K, k = i % K;
    float a = (n < N) ? src[(size_t)k*N + n] : 0.0f;
    __nv_bfloat16 h, l; split_bf16(a, &h, &l);
    dh[i] = h; dl[i] = l;
}

// ================= GEMM v2 (proven): 128x128 tile, 512 threads, BK=32 — inproj =================
#define B2_OFF_AL 10240
#define B2_OFF_BH 20480
#define B2_OFF_BL 30720
#define BUF2_SZ   40960

__global__ void __launch_bounds__(512, 1)
k_mmagemm512(const __nv_bfloat16* __restrict__ Ah, const __nv_bfloat16* __restrict__ Al,
             const __nv_bfloat16* __restrict__ Bh, const __nv_bfloat16* __restrict__ Bl,
             const __nv_bfloat16* __restrict__ B2h, const __nv_bfloat16* __restrict__ B2l,
             float* __restrict__ Cf, int Kfull, int Nact, int Nstride) {
    extern __shared__ char smem[];
    uint32_t sbase = smem_u32(smem);
    int tid = threadIdx.x;
    int wid = tid >> 5, lane = tid & 31;
    int wm = wid >> 2, wn = wid & 3;
    int m0 = blockIdx.y * 128, n0 = blockIdx.x * 128;
    int NC = Kfull >> 5;

    const __nv_bfloat16* bh = (m0 >= MFWD) ? B2h : Bh;
    const __nv_bfloat16* bl = (m0 >= MFWD) ? B2l : Bl;

    float acc[2][4][4];
#pragma unroll
    for (int i = 0; i < 2; i++)
#pragma unroll
        for (int j = 0; j < 4; j++)
#pragma unroll
            for (int q = 0; q < 4; q++) acc[i][j][q] = 0.0f;

    int lrow = tid >> 2, lc16 = tid & 3;
    auto issue = [&](int c) {
        int kb = c*32;
        uint32_t sb = sbase + (c & 1)*BUF2_SZ;
        uint32_t d = sb + lrow*PADB + lc16*16;
        size_t go = (size_t)lrow*Kfull + kb + lc16*8;
        cp_async16(d,             Ah + (size_t)m0*Kfull + go);
        cp_async16(d + B2_OFF_AL, Al + (size_t)m0*Kfull + go);
        uint32_t db = sb + B2_OFF_BH + lrow*PADB + lc16*16;
        cp_async16(db,                           bh + (size_t)n0*Kfull + go);
        cp_async16(db + (B2_OFF_BL - B2_OFF_BH), bl + (size_t)n0*Kfull + go);
        CP_COMMIT();
    };

    issue(0);
    int mrow = lane & 15;
    int mcol16 = (lane >> 4) * 16;

    for (int c = 0; c < NC; c++) {
        CP_WAIT0();
        __syncthreads();
        if (c + 1 < NC) issue(c + 1);
        uint32_t sb = sbase + (c & 1)*BUF2_SZ;
#pragma unroll
        for (int ks = 0; ks < 2; ks++) {
            uint32_t ah[2][4], al[2][4], bhf[2][4], blf[2][4];
#pragma unroll
            for (int tm = 0; tm < 2; tm++) {
                uint32_t aaddr = sb + (wm*32 + tm*16 + mrow)*PADB + ks*32 + mcol16;
                ldsm_x4(ah[tm], aaddr);
                ldsm_x4(al[tm], aaddr + B2_OFF_AL);
            }
#pragma unroll
            for (int tn = 0; tn < 2; tn++) {
                uint32_t baddr = sb + B2_OFF_BH + (wn*32 + tn*16 + mrow)*PADB + ks*32 + mcol16;
                ldsm_x4(bhf[tn], baddr);
                ldsm_x4(blf[tn], baddr + (B2_OFF_BL - B2_OFF_BH));
            }
#pragma unroll
            for (int tm = 0; tm < 2; tm++)
#pragma unroll
                for (int tn = 0; tn < 2; tn++)
#pragma unroll
                    for (int h = 0; h < 2; h++) {
                        int j = tn*2 + h;
                        mma_bf16(acc[tm][j], ah[tm], bhf[tn][h], bhf[tn][h+2]);
                        mma_bf16(acc[tm][j], ah[tm], blf[tn][h], blf[tn][h+2]);
                        mma_bf16(acc[tm][j], al[tm], bhf[tn][h], bhf[tn][h+2]);
                    }
        }
    }

    int lr = lane >> 2;
    int lc2 = (lane & 3) * 2;
#pragma unroll
    for (int tm = 0; tm < 2; tm++) {
        int row0 = m0 + wm*32 + tm*16 + lr;
#pragma unroll
        for (int j = 0; j < 4; j++) {
            int n = n0 + wn*32 + j*8 + lc2;
            if (n < Nact) {
                *reinterpret_cast<float2*>(Cf + (size_t)row0*Nstride + n) =
                    make_float2(acc[tm][j][0], acc[tm][j][1]);
                *reinterpret_cast<float2*>(Cf + (size_t)(row0+8)*Nstride + n) =
                    make_float2(acc[tm][j][2], acc[tm][j][3]);
            }
        }
    }
}

// ================= GEMM v1 (proven): 128x64 tile, 256 threads, occ 2 =================
// MODE 0: outproj residual +=, split hf/hb. MODE 1: final +bias -> out. MODE 2: patch split-K partials.
#define OFF_AL 10240
#define OFF_BH 20480
#define OFF_BL 25600
#define BUF_SZ 30720

template<int MODE>
__global__ void __launch_bounds__(256, 2)
k_mmagemm64(const __nv_bfloat16* __restrict__ Ah, const __nv_bfloat16* __restrict__ Al,
            const __nv_bfloat16* __restrict__ Bh, const __nv_bfloat16* __restrict__ Bl,
            const __nv_bfloat16* __restrict__ B2h, const __nv_bfloat16* __restrict__ B2l,
            float* __restrict__ Cf, float* __restrict__ Cb,
            const float* __restrict__ bias, int Kchunk, int Kfull) {
    extern __shared__ char smem[];
    uint32_t sbase = smem_u32(smem);
    int tid = threadIdx.x;
    int wid = tid >> 5, lane = tid & 31;
    int wm = wid >> 1, wn = wid & 1;
    int m0 = blockIdx.y * 128, n0 = blockIdx.x * 64;
    int kbase = blockIdx.z * Kchunk;
    int NC = Kchunk >> 5;

    const __nv_bfloat16* bh = (MODE == 0 && m0 >= MFWD) ? B2h : Bh;
    const __nv_bfloat16* bl = (MODE == 0 && m0 >= MFWD) ? B2l : Bl;

    float acc[2][4][4];
#pragma unroll
    for (int i = 0; i < 2; i++)
#pragma unroll
        for (int j = 0; j < 4; j++)
#pragma unroll
            for (int q = 0; q < 4; q++) acc[i][j][q] = 0.0f;

    auto issue = [&](int c) {
        int kb = kbase + c*32;
        uint32_t sb = sbase + (c & 1)*BUF_SZ;
#pragma unroll
        for (int it = 0; it < 2; it++) {
            int sg = it*256 + tid;
            int row = sg >> 2, c16 = sg & 3;
            uint32_t d = sb + row*PADB + c16*16;
            cp_async16(d,          Ah + (size_t)(m0 + row)*Kfull + kb + c16*8);
            cp_async16(d + OFF_AL, Al + (size_t)(m0 + row)*Kfull + kb + c16*8);
        }
        {
            int row = tid >> 2, c16 = tid & 3;
            uint32_t d = sb + OFF_BH + row*PADB + c16*16;
            cp_async16(d, bh + (size_t)(n0 + row)*Kfull + kb + c16*8);
            cp_async16(d + (OFF_BL - OFF_BH), bl + (size_t)(n0 + row)*Kfull + kb + c16*8);
        }
        CP_COMMIT();
    };

    issue(0);
    int lrow = lane & 15;
    int lcol16 = (lane >> 4) * 16;

    for (int c = 0; c < NC; c++) {
        CP_WAIT0();
        __syncthreads();
        if (c + 1 < NC) issue(c + 1);
        uint32_t sb = sbase + (c & 1)*BUF_SZ;
#pragma unroll
        for (int ks = 0; ks < 2; ks++) {
            uint32_t ah[2][4], al[2][4], bhf[2][4], blf[2][4];
#pragma unroll
            for (int tm = 0; tm < 2; tm++) {
                uint32_t aaddr = sb + (wm*32 + tm*16 + lrow)*PADB + ks*32 + lcol16;
                ldsm_x4(ah[tm], aaddr);
                ldsm_x4(al[tm], aaddr + OFF_AL);
            }
#pragma unroll
            for (int tn = 0; tn < 2; tn++) {
                uint32_t baddr = sb + OFF_BH + (wn*32 + tn*16 + lrow)*PADB + ks*32 + lcol16;
                ldsm_x4(bhf[tn], baddr);
                ldsm_x4(blf[tn], baddr + (OFF_BL - OFF_BH));
            }
#pragma unroll
            for (int tm = 0; tm < 2; tm++)
#pragma unroll
                for (int tn = 0; tn < 2; tn++)
#pragma unroll
                    for (int h = 0; h < 2; h++) {
                        int j = tn*2 + h;
                        mma_bf16(acc[tm][j], ah[tm], bhf[tn][h], bhf[tn][h+2]);
                        mma_bf16(acc[tm][j], ah[tm], blf[tn][h], blf[tn][h+2]);
                        mma_bf16(acc[tm][j], al[tm], bhf[tn][h], bhf[tn][h+2]);
                    }
        }
    }

    int lr = lane >> 2;
    int lc2 = (lane & 3) * 2;
#pragma unroll
    for (int tm = 0; tm < 2; tm++) {
        int row0 = m0 + wm*32 + tm*16 + lr;
#pragma unroll
        for (int j = 0; j < 4; j++) {
            int n = n0 + wn*32 + j*8 + lc2;
            if (MODE == 0) {
#pragma unroll
                for (int half = 0; half < 2; half++) {
                    int m = row0 + half*8;
                    float* p = (m < MFWD) ? (Cf + (size_t)m*DM + n)
                                          : (Cb + (size_t)(m - MFWD)*DM + n);
                    float2 r = *reinterpret_cast<float2*>(p);
                    r.x += acc[tm][j][half*2 + 0];
                    r.y += acc[tm][j][half*2 + 1];
                    *reinterpret_cast<float2*>(p) = r;
                }
            } else if (MODE == 1) {
                float b0 = bias[n], b1 = bias[n+1];
                *reinterpret_cast<float2*>(Cf + (size_t)row0*128 + n) =
                    make_float2(acc[tm][j][0] + b0, acc[tm][j][1] + b1);
                *reinterpret_cast<float2*>(Cf + (size_t)(row0+8)*128 + n) =
                    make_float2(acc[tm][j][2] + b0, acc[tm][j][3] + b1);
            } else {
                float* Cp = Cf + (size_t)blockIdx.z * MPATCH * DM;
                *reinterpret_cast<float2*>(Cp + (size_t)row0*DM + n) =
                    make_float2(acc[tm][j][0], acc[tm][j][1]);
                *reinterpret_cast<float2*>(Cp + (size_t)(row0+8)*DM + n) =
                    make_float2(acc[tm][j][2], acc[tm][j][3]);
            }
        }
    }
}

// ---------------- fused: patch split-K reduce + bias + aux + mask fill ----------------
__global__ void k_patchfix(const float* __restrict__ pp, const float* __restrict__ bias,
                           const float* __restrict__ aux, const float* __restrict__ mask_token,
                           float* __restrict__ hf, float* __restrict__ hb) {
    int idx = blockIdx.x * 256 + threadIdx.x;
    int m = idx >> 8, n = idx & 255;
    float v = bias[n];
#pragma unroll
    for (int z = 0; z < KSPLIT; z++) v += pp[(size_t)z*MPATCH*DM + idx];
    int b = m / NMASK, j = m % NMASK;
    hf[((size_t)b*NTOK + j)*DM + n] = v + aux[b*DM + n];
    if (idx < BB*TBWD*DM) {
        int c = idx & 255;
        int jj = (idx >> 8) & 127;
        int bb = idx >> 15;
        float mv = mask_token[c] + aux[bb*DM + c];
        hf[((size_t)bb*NTOK + NMASK + jj)*DM + c] = mv;
        hb[((size_t)bb*TBWD + jj)*DM + c] = mv;
    }
}

// ---------------- combined rmsnorm -> bf16 hi/lo ----------------
__global__ void k_rmsnorm2(const float* __restrict__ hf, const float* __restrict__ hb,
                           const float* __restrict__ wf, const float* __restrict__ wb,
                           __nv_bfloat16* __restrict__ uh, __nv_bfloat16* __restrict__ ul) {
    int m = blockIdx.x;
    int c = threadIdx.x; // 256
    const float* in = (m < MFWD) ? (hf + (size_t)m*DM) : (hb + (size_t)(m-MFWD)*DM);
    const float* w  = (m < MFWD) ? wf : wb;
    float v = in[c];
    float s = v*v;
#pragma unroll
    for (int o = 16; o > 0; o >>= 1) s += __shfl_xor_sync(0xffffffffu, s, o);
    __shared__ float ws[8];
    if ((c & 31) == 0) ws[c >> 5] = s;
    __syncthreads();
    float tot = 0.0f;
#pragma unroll
    for (int i = 0; i < 8; i++) tot += ws[i];
    float rs = rsqrtf(tot / (float)DM + 1e-5f);
    float o = v * rs * w[c];
    __nv_bfloat16 h, l; split_bf16(o, &h, &l);
    uh[(size_t)m*DM + c] = h; ul[(size_t)m*DM + c] = l;
}

// ---------------- conv + dt: 8 tokens per block, rolling register window ----------------
#define TC 8
__global__ void __launch_bounds__(CONVDIM, 2)
k_convdt2(const float* __restrict__ zx,
          const float* __restrict__ cwf, const float* __restrict__ cbf,
          const float* __restrict__ dtbf,
          const float* __restrict__ cwb, const float* __restrict__ cbb,
          const float* __restrict__ dtbb,
          float* __restrict__ X, float* __restrict__ Bo, float* __restrict__ Co,
          float* __restrict__ dto) {
    int m0 = blockIdx.x * TC;
    int c = threadIdx.x;
    int t0;
    const float *cw, *cb, *dtb;
    if (m0 < MFWD) { t0 = m0 & (TFWD-1); cw = cwf; cb = cbf; dtb = dtbf; }
    else           { t0 = (m0 - MFWD) & (TBWD-1); cw = cwb; cb = cbb; dtb = dtbb; }
    float w0 = cw[c*4], w1 = cw[c*4+1], w2 = cw[c*4+2], w3 = cw[c*4+3];
    float bi = cb[c];
    float win[TC+3];
#pragma unroll
    for (int i = 0; i < TC+3; i++) {
        int tt = t0 - 3 + i;
        win[i] = (tt >= 0) ? zx[((size_t)(m0 - 3 + i))*DPROJ + DIN + c] : 0.0f;
    }
#pragma unroll
    for (int j = 0; j < TC; j++) {
        float acc = bi + win[j]*w0 + win[j+1]*w1 + win[j+2]*w2 + win[j+3]*w3;
        float v = silu_f(acc);
        int m = m0 + j;
        if (c < DIN)             X[(size_t)m*DIN + c] = v;
        else if (c < DIN+DSTATE) Bo[m*DSTATE + (c-DIN)] = v;
        else                     Co[m*DSTATE + (c-DIN-DSTATE)] = v;
    }
    if (c < NH) {
        float db = dtb[c];
#pragma unroll
        for (int j = 0; j < TC; j++) {
            int m = m0 + j;
            dto[m*NH + c] = softplus_f(zx[(size_t)m*DPROJ + 2*DIN + 2*DSTATE + c] + db);
        }
    }
}

// ---------------- scan v5 (proven R13): depth-4 register prefetch pipeline ----------------
__global__ void __launch_bounds__(512)
k_scan5(const float* __restrict__ X, const float* __restrict__ Bb, const float* __restrict__ Cb,
        const float* __restrict__ dtb,
        const float* __restrict__ Alogf, const float* __restrict__ Dpf,
        const float* __restrict__ Alogb, const float* __restrict__ Dpb) {
    float* __restrict__ Y = g_y;
    int blk = blockIdx.x;
    int T, rowbase, h;
    float A, Dh;
    if (blk < 64) {
        int b = blk >> 3; h = blk & 7;
        T = TFWD; rowbase = b * TFWD;
        A = -expf(Alogf[h]); Dh = Dpf[h];
    } else {
        int b = (blk - 64) >> 3; h = blk & 7;
        T = TBWD; rowbase = MFWD + b * TBWD;
        A = -expf(Alogb[h]); Dh = Dpb[h];
    }
    int wid = threadIdx.x >> 5, lane = threadIdx.x & 31;
    int pg = lane >> 3, ng = lane & 7;
    int p = wid*4 + pg;
    const float4* B4 = reinterpret_cast<const float4*>(Bb);
    const float4* C4 = reinterpret_cast<const float4*>(Cb);

    float4 Brb[4], Crb[4];
    float dtrb[4], xrb[4];
#pragma unroll
    for (int j = 0; j < 4; j++) {
        int rr = rowbase + j;
        Brb[j]  = B4[(size_t)rr*8 + ng];
        Crb[j]  = C4[(size_t)rr*8 + ng];
        dtrb[j] = dtb[(size_t)rr*NH + h];
        xrb[j]  = X[(size_t)rr*DIN + h*HD + p];
    }

    float s0 = 0.f, s1 = 0.f, s2 = 0.f, s3 = 0.f;
    for (int t = 0; t < T; t += 4) {
#pragma unroll
        for (int j = 0; j < 4; j++) {
            int tt = t + j;
            float4 Bv = Brb[j], Cv = Crb[j];
            float dtc = dtrb[j], xc = xrb[j];
            int rn = rowbase + (((tt+4) < T) ? (tt+4) : (T-1));
            Brb[j]  = B4[(size_t)rn*8 + ng];
            Crb[j]  = C4[(size_t)rn*8 + ng];
            dtrb[j] = dtb[(size_t)rn*NH + h];
            xrb[j]  = X[(size_t)rn*DIN + h*HD + p];
            float dA = expf(dtc * A);
            float dx = dtc * xc;
            s0 = s0*dA + dx*Bv.x;
            s1 = s1*dA + dx*Bv.y;
            s2 = s2*dA + dx*Bv.z;
            s3 = s3*dA + dx*Bv.w;
            float y = s0*Cv.x + s1*Cv.y + s2*Cv.z + s3*Cv.w;
            y += __shfl_xor_sync(0xffffffffu, y, 1);
            y += __shfl_xor_sync(0xffffffffu, y, 2);
            y += __shfl_xor_sync(0xffffffffu, y, 4);
            if (ng == 0) Y[(size_t)(rowbase + tt)*DIN + h*HD + p] = y + Dh*xc;
        }
    }
}

// ---------------- combined gated rmsnorm -> bf16 hi/lo ----------------
__global__ void k_gatednorm2(const float* __restrict__ Y, const float* __restrict__ zx,
                             const float* __restrict__ gwf, const float* __restrict__ gwb,
                             __nv_bfloat16* __restrict__ uh, __nv_bfloat16* __restrict__ ul) {
    int m = blockIdx.x;
    int c = threadIdx.x; // 512
    const float* gw = (m < MFWD) ? gwf : gwb;
    float z = zx[(size_t)m*DPROJ + c];
    float g = Y[(size_t)m*DIN + c] * silu_f(z);
    float s = g*g;
#pragma unroll
    for (int o = 16; o > 0; o >>= 1) s += __shfl_xor_sync(0xffffffffu, s, o);
    __shared__ float ws[16];
    if ((c & 31) == 0) ws[c >> 5] = s;
    __syncthreads();
    float tot = 0.0f;
#pragma unroll
    for (int i = 0; i < 16; i++) tot += ws[i];
    float rs = rsqrtf(tot / (float)DIN + 1e-5f);
    float o = g * rs * gw[c];
    __nv_bfloat16 h, l; split_bf16(o, &h, &l);
    uh[(size_t)m*DIN + c] = h; ul[(size_t)m*DIN + c] = l;
}

// ---------------- concat + split for final GEMM ----------------
__global__ void k_catsplit(const float* __restrict__ hf, const float* __restrict__ hb,
                           __nv_bfloat16* __restrict__ uh, __nv_bfloat16* __restrict__ ul) {
    int idx = blockIdx.x * 256 + threadIdx.x;
    int m = idx >> 9, c = idx & 511;
    int b = m >> 7, jj = m & 127;
    float v = (c < 256) ? hf[((size_t)b*NTOK + NMASK + jj)*DM + c]
                        : hb[((size_t)b*TBWD + (127 - jj))*DM + (c - 256)];
    __nv_bfloat16 h, l; split_bf16(v, &h, &l);
    uh[idx] = h; ul[idx] = l;
}

// ================= host =================
extern "C" void kernel_launch(void* const* d_in, const int* in_sizes, int n_in,
                              void* d_out, int out_size) {
    float *aux, *pp, *hf, *hb, *zx, *X, *Bbuf, *Cbuf, *dt, *Y;
    __nv_bfloat16 *pch, *pcl, *uh, *ul, *u2h, *u2l, *wph, *wpl, *wih, *wil, *woh, *wol, *wfh, *wfl;
    cudaGetSymbolAddress((void**)&aux, g_aux);
    cudaGetSymbolAddress((void**)&pp,  g_pp);
    cudaGetSymbolAddress((void**)&hf,  g_hf);
    cudaGetSymbolAddress((void**)&hb,  g_hb);
    cudaGetSymbolAddress((void**)&zx,  g_zx);
    cudaGetSymbolAddress((void**)&X,   g_x);
    cudaGetSymbolAddress((void**)&Bbuf, g_Bb);
    cudaGetSymbolAddress((void**)&Cbuf, g_Cb);
    cudaGetSymbolAddress((void**)&dt,  g_dt);
    cudaGetSymbolAddress((void**)&Y,   g_y);
    cudaGetSymbolAddress((void**)&pch, g_pch);
    cudaGetSymbolAddress((void**)&pcl, g_pcl);
    cudaGetSymbolAddress((void**)&uh,  g_uh);
    cudaGetSymbolAddress((void**)&ul,  g_ul);
    cudaGetSymbolAddress((void**)&u2h, g_u2h);
    cudaGetSymbolAddress((void**)&u2l, g_u2l);
    cudaGetSymbolAddress((void**)&wph, g_wph);
    cudaGetSymbolAddress((void**)&wpl, g_wpl);
    cudaGetSymbolAddress((void**)&wih, g_wih);
    cudaGetSymbolAddress((void**)&wil, g_wil);
    cudaGetSymbolAddress((void**)&woh, g_woh);
    cudaGetSymbolAddress((void**)&wol, g_wol);
    cudaGetSymbolAddress((void**)&wfh, g_wfh);
    cudaGetSymbolAddress((void**)&wfl, g_wfl);

    const float* x_prefix   = (const float*)d_in[0];
    const float* y_aux      = (const float*)d_in[1];
    const float* pre_conv_w = (const float*)d_in[2];
    const float* pre_conv_b = (const float*)d_in[3];
    const float* patch_w    = (const float*)d_in[4];
    const float* patch_b    = (const float*)d_in[5];
    const float* mask_token = (const float*)d_in[6];
    const float* aux_w      = (const float*)d_in[7];
    const float* aux_b      = (const float*)d_in[8];

    const float *patch_out_w, *patch_out_b;
    int fbase, bbase;
    if (n_in > 9 && in_sizes[9] == 65536) {
        patch_out_w = (const float*)d_in[9];
        patch_out_b = (const float*)d_in[10];
        fbase = 11; bbase = 20;
    } else {
        fbase = 9; bbase = 18;
        patch_out_w = (const float*)d_in[27];
        patch_out_b = (const float*)d_in[28];
    }
    const float* fW[9]; const float* bW[9];
    for (int i = 0; i < 9; i++) { fW[i] = (const float*)d_in[fbase+i]; bW[i] = (const float*)d_in[bbase+i]; }

    cudaFuncSetAttribute(k_mmagemm512, cudaFuncAttributeMaxDynamicSharedMemorySize, 2*BUF2_SZ);
    cudaFuncSetAttribute(k_mmagemm64<0>, cudaFuncAttributeMaxDynamicSharedMemorySize, 2*BUF_SZ);
    cudaFuncSetAttribute(k_mmagemm64<1>, cudaFuncAttributeMaxDynamicSharedMemorySize, 2*BUF_SZ);
    cudaFuncSetAttribute(k_mmagemm64<2>, cudaFuncAttributeMaxDynamicSharedMemorySize, 2*BUF_SZ);

    // launch order: patch GEMM in profiled slot 4
    k_aux<<<1, 256>>>(y_aux, aux_w, aux_b, aux);                               // 1
    k_cvt_patchw<<<(DM*KPATCH)/256, 256>>>(patch_w, wph, wpl);                 // 2
    k_preconv<<<MPATCH, 256>>>(x_prefix, pre_conv_w, pre_conv_b, pch, pcl);    // 3
    // patch GEMM via occ-2 kernel: grid (256/64, 3072/128, KSPLIT=2) = 192 blocks
    k_mmagemm64<2><<<dim3(DM/64, MPATCH/128, KSPLIT), 256, 2*BUF_SZ>>>(        // 4 (profiled)
        pch, pcl, wph, wpl, wph, wpl, pp, nullptr, nullptr, KCHUNK, KPATCH);
    k_cvt_all<<<dim3((NPADI*DM)/256, 1, 9), 256>>>(fW[1], bW[1], fW[8], bW[8], patch_out_w,
                                                   wih, wil, woh, wol, wfh, wfl);
    k_patchfix<<<(MPATCH*DM)/256, 256>>>(pp, patch_b, aux, mask_token, hf, hb);

    for (int lay = 0; lay < 2; lay++) {
        k_rmsnorm2<<<MTOT, DM>>>(hf, hb, fW[0] + lay*DM, bW[0] + lay*DM, uh, ul);
        k_mmagemm512<<<dim3(NPADI/128, MTOT/128), 512, 2*BUF2_SZ>>>(
            uh, ul,
            wih + (size_t)lay*NPADI*DM,     wil + (size_t)lay*NPADI*DM,
            wih + (size_t)(2+lay)*NPADI*DM, wil + (size_t)(2+lay)*NPADI*DM,
            zx, DM, DPROJ, DPROJ);
        k_convdt2<<<MTOT/TC, CONVDIM>>>(zx,
            fW[2] + lay*CONVDIM*4, fW[3] + lay*CONVDIM, fW[4] + lay*NH,
            bW[2] + lay*CONVDIM*4, bW[3] + lay*CONVDIM, bW[4] + lay*NH,
            X, Bbuf, Cbuf, dt);
        k_scan5<<<128, 512>>>(X, Bbuf, Cbuf, dt,
            fW[5] + lay*NH, fW[6] + lay*NH, bW[5] + lay*NH, bW[6] + lay*NH);
        k_gatednorm2<<<MTOT, DIN>>>(Y, zx, fW[7] + lay*DIN, bW[7] + lay*DIN, u2h, u2l);
        k_mmagemm64<0><<<dim3(DM/64, MTOT/128), 256, 2*BUF_SZ>>>(
            u2h, u2l,
            woh + (size_t)lay*DM*DIN,     wol + (size_t)lay*DM*DIN,
            woh + (size_t)(2+lay)*DM*DIN, wol + (size_t)(2+lay)*DM*DIN,
            hf, hb, nullptr, DIN, DIN);
    }

    // final: concat+split, then 1024x128 GEMM (K=512) straight into d_out
    k_catsplit<<<(1024*512)/256, 256>>>(hf, hb, u2h, u2l);
    k_mmagemm64<1><<<dim3(2, 8), 256, 2*BUF_SZ>>>(
        u2h, u2l, wfh, wfl, wfh, wfl, (float*)d_out, nullptr, patch_out_b, 2*DM, 2*DM);

    (void)in_sizes; (void)n_in; (void)out_size;
}

// round 16
// speedup vs baseline: 1.5642x; 1.5642x over previous
#include <cuda_runtime.h>
#include <cuda_bf16.h>
#include <math.h>
#include <stdint.h>

// ---------------- problem constants ----------------
#define BB 8
#define TPRE 6144
#define CIN 8
#define OUTLEN 2048
#define OUTC 8
#define AUXD 16
#define DM 256
#define DSTATE 32
#define HD 64
#define DIN 512
#define NH 8
#define CONVDIM 576
#define DPROJ 1096
#define NPADI 1152
#define PATCHN 16
#define NTOK 512
#define NMASK 384
#define TFWD 512
#define TBWD 128
#define MFWD (BB*TFWD)    // 4096
#define MBWD (BB*TBWD)    // 1024
#define MTOT (MFWD+MBWD)  // 5120
#define MPATCH (BB*NMASK) // 3072
#define KPATCH 4096
#define KSPLIT 4
#define KCHUNK 1024

// ---------------- scratch ----------------
__device__ __align__(256) float g_aux[BB*DM];
__device__ __align__(256) float g_pp[(size_t)KSPLIT*MPATCH*DM];
__device__ __align__(256) float g_hf[(size_t)BB*NTOK*DM];
__device__ __align__(256) float g_hb[(size_t)BB*TBWD*DM];
__device__ __align__(256) float g_zx[(size_t)MTOT*DPROJ];
__device__ __align__(256) float g_x [(size_t)MTOT*DIN];
__device__ __align__(256) float g_Bb[(size_t)MTOT*DSTATE];
__device__ __align__(256) float g_Cb[(size_t)MTOT*DSTATE];
__device__ __align__(256) float g_dt[(size_t)MTOT*NH];
__device__ __align__(256) float g_y [(size_t)MTOT*DIN];

__device__ __align__(256) __nv_bfloat16 g_pch[(size_t)MPATCH*KPATCH];
__device__ __align__(256) __nv_bfloat16 g_pcl[(size_t)MPATCH*KPATCH];
__device__ __align__(256) __nv_bfloat16 g_uh[(size_t)MTOT*DM];
__device__ __align__(256) __nv_bfloat16 g_ul[(size_t)MTOT*DM];
__device__ __align__(256) __nv_bfloat16 g_u2h[(size_t)MTOT*DIN];
__device__ __align__(256) __nv_bfloat16 g_u2l[(size_t)MTOT*DIN];
__device__ __align__(256) __nv_bfloat16 g_wph[(size_t)DM*KPATCH];
__device__ __align__(256) __nv_bfloat16 g_wpl[(size_t)DM*KPATCH];
__device__ __align__(256) __nv_bfloat16 g_wih[(size_t)4*NPADI*DM];
__device__ __align__(256) __nv_bfloat16 g_wil[(size_t)4*NPADI*DM];
__device__ __align__(256) __nv_bfloat16 g_woh[(size_t)4*DM*DIN];
__device__ __align__(256) __nv_bfloat16 g_wol[(size_t)4*DM*DIN];
__device__ __align__(256) __nv_bfloat16 g_wfh[(size_t)128*2*DM];
__device__ __align__(256) __nv_bfloat16 g_wfl[(size_t)128*2*DM];

__device__ __forceinline__ float silu_f(float v) { return v / (1.0f + expf(-v)); }
__device__ __forceinline__ float softplus_f(float v) { return (v > 20.0f) ? v : log1pf(expf(v)); }

__device__ __forceinline__ void split_bf16(float a, __nv_bfloat16* h, __nv_bfloat16* l) {
    __nv_bfloat16 hh = __float2bfloat16_rn(a);
    *h = hh;
    *l = __float2bfloat16_rn(a - __bfloat162float(hh));
}

// ---------------- baseline-PTX helpers ----------------
__device__ __forceinline__ uint32_t smem_u32(const void* p) {
    uint32_t a;
    asm("{ .reg .u64 t; cvta.to.shared.u64 t, %1; cvt.u32.u64 %0, t; }" : "=r"(a) : "l"(p));
    return a;
}
__device__ __forceinline__ void cp_async16(uint32_t dst, const void* src) {
    asm volatile("cp.async.cg.shared.global [%0], [%1], 16;" :: "r"(dst), "l"(src));
}
#define CP_COMMIT() asm volatile("cp.async.commit_group;" ::: "memory")
#define CP_WAIT0()  asm volatile("cp.async.wait_group 0;" ::: "memory")

__device__ __forceinline__ void ldsm_x4(uint32_t* r, uint32_t addr) {
    asm volatile("ldmatrix.sync.aligned.m8n8.x4.shared.b16 {%0,%1,%2,%3}, [%4];"
                 : "=r"(r[0]), "=r"(r[1]), "=r"(r[2]), "=r"(r[3]) : "r"(addr));
}
__device__ __forceinline__ void mma_bf16(float* d, const uint32_t* a, uint32_t b0, uint32_t b1) {
    asm volatile("mma.sync.aligned.m16n8k16.row.col.f32.bf16.bf16.f32 "
        "{%0,%1,%2,%3}, {%4,%5,%6,%7}, {%8,%9}, {%0,%1,%2,%3};"
        : "+f"(d[0]), "+f"(d[1]), "+f"(d[2]), "+f"(d[3])
        : "r"(a[0]), "r"(a[1]), "r"(a[2]), "r"(a[3]), "r"(b0), "r"(b1));
}

#define PADB 80

// ---------------- aux bias ----------------
__global__ void k_aux(const float* __restrict__ y_aux, const float* __restrict__ aux_w,
                      const float* __restrict__ aux_b, float* __restrict__ out) {
    __shared__ float ys[BB*AUXD];
    int c = threadIdx.x;
    if (c < BB*AUXD) ys[c] = y_aux[c];
    __syncthreads();
    float wcol[AUXD];
#pragma unroll
    for (int i = 0; i < AUXD; i++) wcol[i] = aux_w[i*DM + c];
    float bias = aux_b[c];
    for (int b = 0; b < BB; b++) {
        float acc = bias;
#pragma unroll
        for (int i = 0; i < AUXD; i++) acc += ys[b*AUXD + i] * wcol[i];
        out[b*DM + c] = silu_f(acc);
    }
}

// ---------------- pre-conv -> bf16 hi/lo ----------------
__global__ void k_preconv(const float* __restrict__ xp, const float* __restrict__ w,
                          const float* __restrict__ bias,
                          __nv_bfloat16* __restrict__ ph, __nv_bfloat16* __restrict__ pl) {
    int m = blockIdx.x;
    int b = m / NMASK, j = m % NMASK;
    int t0 = j * PATCHN;
    __shared__ float xs[20][CIN];
    int tid = threadIdx.x;
    if (tid < 20*CIN) {
        int tt = t0 - 2 + tid / CIN;
        int i = tid % CIN;
        xs[tid/CIN][i] = (tt >= 0 && tt < TPRE) ? xp[((size_t)b*TPRE + tt)*CIN + i] : 0.0f;
    }
    __syncthreads();
    int c = tid;
    float wr[CIN*5];
#pragma unroll
    for (int q = 0; q < CIN*5; q++) wr[q] = w[c*CIN*5 + q];
    float bi = bias[c];
    size_t ob = (size_t)m*KPATCH + c*PATCHN;
#pragma unroll
    for (int k = 0; k < PATCHN; k++) {
        float acc = bi;
#pragma unroll
        for (int i = 0; i < CIN; i++)
#pragma unroll
            for (int q = 0; q < 5; q++)
                acc += xs[k+q][i] * wr[i*5 + q];
        float v = silu_f(acc);
        __nv_bfloat16 h, l; split_bf16(v, &h, &l);
        ph[ob + k] = h; pl[ob + k] = l;
    }
}

// ---------------- merged weight conversions ----------------
// z 0..3 inproj slots (transpose); z 4..7 outproj (transpose); z 8 final (transpose);
// z 9..12 patch_w (plain copy+split, quarter each)
__global__ void k_cvt_all(const float* __restrict__ fWi, const float* __restrict__ bWi,
                          const float* __restrict__ fWo, const float* __restrict__ bWo,
                          const float* __restrict__ pow_, const float* __restrict__ patchw,
                          __nv_bfloat16* __restrict__ wih, __nv_bfloat16* __restrict__ wil,
                          __nv_bfloat16* __restrict__ woh, __nv_bfloat16* __restrict__ wol,
                          __nv_bfloat16* __restrict__ wfh, __nv_bfloat16* __restrict__ wfl,
                          __nv_bfloat16* __restrict__ wph, __nv_bfloat16* __restrict__ wpl) {
    int z = blockIdx.z;
    int i = blockIdx.x * 256 + threadIdx.x;
    if (z >= 9) {
        size_t off = (size_t)(z - 9) * (DM*KPATCH/4);
        if (i >= DM*KPATCH/4) return;
        float a = patchw[off + i];
        __nv_bfloat16 h, l; split_bf16(a, &h, &l);
        wph[off + i] = h; wpl[off + i] = l;
        return;
    }
    const float* src; int K, N, Npad; __nv_bfloat16 *dh, *dl;
    if (z < 4) {
        src = ((z >> 1) ? bWi : fWi) + (size_t)(z & 1)*DM*DPROJ;
        K = DM; N = DPROJ; Npad = NPADI;
        dh = wih + (size_t)z*NPADI*DM; dl = wil + (size_t)z*NPADI*DM;
    } else if (z < 8) {
        int s = z - 4;
        src = ((s >> 1) ? bWo : fWo) + (size_t)(s & 1)*DIN*DM;
        K = DIN; N = DM; Npad = DM;
        dh = woh + (size_t)s*DM*DIN; dl = wol + (size_t)s*DM*DIN;
    } else {
        src = pow_; K = 2*DM; N = 128; Npad = 128; dh = wfh; dl = wfl;
    }
    if (i >= Npad*K) return;
    int n = i / K, k = i % K;
    float a = (n < N) ? src[(size_t)k*N + n] : 0.0f;
    __nv_bfloat16 h, l; split_bf16(a, &h, &l);
    dh[i] = h; dl[i] = l;
}

// ================= GEMM v2 (proven): 128x128 tile, 512 threads, BK=32 =================
#define B2_OFF_AL 10240
#define B2_OFF_BH 20480
#define B2_OFF_BL 30720
#define BUF2_SZ   40960

template<int MODE>
__global__ void __launch_bounds__(512, 1)
k_mmagemm512(const __nv_bfloat16* __restrict__ Ah, const __nv_bfloat16* __restrict__ Al,
             const __nv_bfloat16* __restrict__ Bh, const __nv_bfloat16* __restrict__ Bl,
             const __nv_bfloat16* __restrict__ B2h, const __nv_bfloat16* __restrict__ B2l,
             float* __restrict__ Cf, int Kchunk, int Kfull, int Nact, int Nstride) {
    extern __shared__ char smem[];
    uint32_t sbase = smem_u32(smem);
    int tid = threadIdx.x;
    int wid = tid >> 5, lane = tid & 31;
    int wm = wid >> 2, wn = wid & 3;
    int m0 = blockIdx.y * 128, n0 = blockIdx.x * 128;
    int kbase = blockIdx.z * Kchunk;
    int NC = Kchunk >> 5;

    const __nv_bfloat16* bh = (MODE == 1 && m0 >= MFWD) ? B2h : Bh;
    const __nv_bfloat16* bl = (MODE == 1 && m0 >= MFWD) ? B2l : Bl;

    float acc[2][4][4];
#pragma unroll
    for (int i = 0; i < 2; i++)
#pragma unroll
        for (int j = 0; j < 4; j++)
#pragma unroll
            for (int q = 0; q < 4; q++) acc[i][j][q] = 0.0f;

    int lrow = tid >> 2, lc16 = tid & 3;
    auto issue = [&](int c) {
        int kb = kbase + c*32;
        uint32_t sb = sbase + (c & 1)*BUF2_SZ;
        uint32_t d = sb + lrow*PADB + lc16*16;
        size_t go = (size_t)lrow*Kfull + kb + lc16*8;
        cp_async16(d,             Ah + (size_t)m0*Kfull + go);
        cp_async16(d + B2_OFF_AL, Al + (size_t)m0*Kfull + go);
        uint32_t db = sb + B2_OFF_BH + lrow*PADB + lc16*16;
        cp_async16(db,                           bh + (size_t)n0*Kfull + go);
        cp_async16(db + (B2_OFF_BL - B2_OFF_BH), bl + (size_t)n0*Kfull + go);
        CP_COMMIT();
    };

    issue(0);
    int mrow = lane & 15;
    int mcol16 = (lane >> 4) * 16;

    for (int c = 0; c < NC; c++) {
        CP_WAIT0();
        __syncthreads();
        if (c + 1 < NC) issue(c + 1);
        uint32_t sb = sbase + (c & 1)*BUF2_SZ;
#pragma unroll
        for (int ks = 0; ks < 2; ks++) {
            uint32_t ah[2][4], al[2][4], bhf[2][4], blf[2][4];
#pragma unroll
            for (int tm = 0; tm < 2; tm++) {
                uint32_t aaddr = sb + (wm*32 + tm*16 + mrow)*PADB + ks*32 + mcol16;
                ldsm_x4(ah[tm], aaddr);
                ldsm_x4(al[tm], aaddr + B2_OFF_AL);
            }
#pragma unroll
            for (int tn = 0; tn < 2; tn++) {
                uint32_t baddr = sb + B2_OFF_BH + (wn*32 + tn*16 + mrow)*PADB + ks*32 + mcol16;
                ldsm_x4(bhf[tn], baddr);
                ldsm_x4(blf[tn], baddr + (B2_OFF_BL - B2_OFF_BH));
            }
#pragma unroll
            for (int tm = 0; tm < 2; tm++)
#pragma unroll
                for (int tn = 0; tn < 2; tn++)
#pragma unroll
                    for (int h = 0; h < 2; h++) {
                        int j = tn*2 + h;
                        mma_bf16(acc[tm][j], ah[tm], bhf[tn][h], bhf[tn][h+2]);
                        mma_bf16(acc[tm][j], ah[tm], blf[tn][h], blf[tn][h+2]);
                        mma_bf16(acc[tm][j], al[tm], bhf[tn][h], bhf[tn][h+2]);
                    }
        }
    }

    int lr = lane >> 2;
    int lc2 = (lane & 3) * 2;
#pragma unroll
    for (int tm = 0; tm < 2; tm++) {
        int row0 = m0 + wm*32 + tm*16 + lr;
#pragma unroll
        for (int j = 0; j < 4; j++) {
            int n = n0 + wn*32 + j*8 + lc2;
            if (MODE == 0) {
                float* Cp = Cf + (size_t)blockIdx.z * MPATCH * DM;
                *reinterpret_cast<float2*>(Cp + (size_t)row0*DM + n) =
                    make_float2(acc[tm][j][0], acc[tm][j][1]);
                *reinterpret_cast<float2*>(Cp + (size_t)(row0+8)*DM + n) =
                    make_float2(acc[tm][j][2], acc[tm][j][3]);
            } else {
                if (n < Nact) {
                    *reinterpret_cast<float2*>(Cf + (size_t)row0*Nstride + n) =
                        make_float2(acc[tm][j][0], acc[tm][j][1]);
                    *reinterpret_cast<float2*>(Cf + (size_t)(row0+8)*Nstride + n) =
                        make_float2(acc[tm][j][2], acc[tm][j][3]);
                }
            }
        }
    }
}

// ================= GEMM v1 (proven): 128x64 tile, 256 threads =================
// MODE 0: outproj residual +=, split hf/hb. MODE 1: final +bias -> out.
#define OFF_AL 10240
#define OFF_BH 20480
#define OFF_BL 25600
#define BUF_SZ 30720

template<int MODE>
__global__ void __launch_bounds__(256, 2)
k_mmagemm64(const __nv_bfloat16* __restrict__ Ah, const __nv_bfloat16* __restrict__ Al,
            const __nv_bfloat16* __restrict__ Bh, const __nv_bfloat16* __restrict__ Bl,
            const __nv_bfloat16* __restrict__ B2h, const __nv_bfloat16* __restrict__ B2l,
            float* __restrict__ Cf, float* __restrict__ Cb,
            const float* __restrict__ bias, int Kfull) {
    extern __shared__ char smem[];
    uint32_t sbase = smem_u32(smem);
    int tid = threadIdx.x;
    int wid = tid >> 5, lane = tid & 31;
    int wm = wid >> 1, wn = wid & 1;
    int m0 = blockIdx.y * 128, n0 = blockIdx.x * 64;
    int NC = Kfull >> 5;

    const __nv_bfloat16* bh = (MODE == 0 && m0 >= MFWD) ? B2h : Bh;
    const __nv_bfloat16* bl = (MODE == 0 && m0 >= MFWD) ? B2l : Bl;

    float acc[2][4][4];
#pragma unroll
    for (int i = 0; i < 2; i++)
#pragma unroll
        for (int j = 0; j < 4; j++)
#pragma unroll
            for (int q = 0; q < 4; q++) acc[i][j][q] = 0.0f;

    auto issue = [&](int c) {
        int kb = c*32;
        uint32_t sb = sbase + (c & 1)*BUF_SZ;
#pragma unroll
        for (int it = 0; it < 2; it++) {
            int sg = it*256 + tid;
            int row = sg >> 2, c16 = sg & 3;
            uint32_t d = sb + row*PADB + c16*16;
            cp_async16(d,          Ah + (size_t)(m0 + row)*Kfull + kb + c16*8);
            cp_async16(d + OFF_AL, Al + (size_t)(m0 + row)*Kfull + kb + c16*8);
        }
        {
            int row = tid >> 2, c16 = tid & 3;
            uint32_t d = sb + OFF_BH + row*PADB + c16*16;
            cp_async16(d, bh + (size_t)(n0 + row)*Kfull + kb + c16*8);
            cp_async16(d + (OFF_BL - OFF_BH), bl + (size_t)(n0 + row)*Kfull + kb + c16*8);
        }
        CP_COMMIT();
    };

    issue(0);
    int lrow = lane & 15;
    int lcol16 = (lane >> 4) * 16;

    for (int c = 0; c < NC; c++) {
        CP_WAIT0();
        __syncthreads();
        if (c + 1 < NC) issue(c + 1);
        uint32_t sb = sbase + (c & 1)*BUF_SZ;
#pragma unroll
        for (int ks = 0; ks < 2; ks++) {
            uint32_t ah[2][4], al[2][4], bhf[2][4], blf[2][4];
#pragma unroll
            for (int tm = 0; tm < 2; tm++) {
                uint32_t aaddr = sb + (wm*32 + tm*16 + lrow)*PADB + ks*32 + lcol16;
                ldsm_x4(ah[tm], aaddr);
                ldsm_x4(al[tm], aaddr + OFF_AL);
            }
#pragma unroll
            for (int tn = 0; tn < 2; tn++) {
                uint32_t baddr = sb + OFF_BH + (wn*32 + tn*16 + lrow)*PADB + ks*32 + lcol16;
                ldsm_x4(bhf[tn], baddr);
                ldsm_x4(blf[tn], baddr + (OFF_BL - OFF_BH));
            }
#pragma unroll
            for (int tm = 0; tm < 2; tm++)
#pragma unroll
                for (int tn = 0; tn < 2; tn++)
#pragma unroll
                    for (int h = 0; h < 2; h++) {
                        int j = tn*2 + h;
                        mma_bf16(acc[tm][j], ah[tm], bhf[tn][h], bhf[tn][h+2]);
                        mma_bf16(acc[tm][j], ah[tm], blf[tn][h], blf[tn][h+2]);
                        mma_bf16(acc[tm][j], al[tm], bhf[tn][h], bhf[tn][h+2]);
                    }
        }
    }

    int lr = lane >> 2;
    int lc2 = (lane & 3) * 2;
#pragma unroll
    for (int tm = 0; tm < 2; tm++) {
        int row0 = m0 + wm*32 + tm*16 + lr;
#pragma unroll
        for (int j = 0; j < 4; j++) {
            int n = n0 + wn*32 + j*8 + lc2;
            if (MODE == 0) {
#pragma unroll
                for (int half = 0; half < 2; half++) {
                    int m = row0 + half*8;
                    float* p = (m < MFWD) ? (Cf + (size_t)m*DM + n)
                                          : (Cb + (size_t)(m - MFWD)*DM + n);
                    float2 r = *reinterpret_cast<float2*>(p);
                    r.x += acc[tm][j][half*2 + 0];
                    r.y += acc[tm][j][half*2 + 1];
                    *reinterpret_cast<float2*>(p) = r;
                }
            } else {
                float b0 = bias[n], b1 = bias[n+1];
                *reinterpret_cast<float2*>(Cf + (size_t)row0*128 + n) =
                    make_float2(acc[tm][j][0] + b0, acc[tm][j][1] + b1);
                *reinterpret_cast<float2*>(Cf + (size_t)(row0+8)*128 + n) =
                    make_float2(acc[tm][j][2] + b0, acc[tm][j][3] + b1);
            }
        }
    }
}

// ---------------- fused: patch split-K reduce + bias + aux + mask fill ----------------
__global__ void k_patchfix(const float* __restrict__ pp, const float* __restrict__ bias,
                           const float* __restrict__ aux, const float* __restrict__ mask_token,
                           float* __restrict__ hf, float* __restrict__ hb) {
    int idx = blockIdx.x * 256 + threadIdx.x;
    int m = idx >> 8, n = idx & 255;
    float v = bias[n];
#pragma unroll
    for (int z = 0; z < KSPLIT; z++) v += pp[(size_t)z*MPATCH*DM + idx];
    int b = m / NMASK, j = m % NMASK;
    hf[((size_t)b*NTOK + j)*DM + n] = v + aux[b*DM + n];
    if (idx < BB*TBWD*DM) {
        int c = idx & 255;
        int jj = (idx >> 8) & 127;
        int bb = idx >> 15;
        float mv = mask_token[c] + aux[bb*DM + c];
        hf[((size_t)bb*NTOK + NMASK + jj)*DM + c] = mv;
        hb[((size_t)bb*TBWD + jj)*DM + c] = mv;
    }
}

// ---------------- combined rmsnorm -> bf16 hi/lo ----------------
__global__ void k_rmsnorm2(const float* __restrict__ hf, const float* __restrict__ hb,
                           const float* __restrict__ wf, const float* __restrict__ wb,
                           __nv_bfloat16* __restrict__ uh, __nv_bfloat16* __restrict__ ul) {
    int m = blockIdx.x;
    int c = threadIdx.x; // 256
    const float* in = (m < MFWD) ? (hf + (size_t)m*DM) : (hb + (size_t)(m-MFWD)*DM);
    const float* w  = (m < MFWD) ? wf : wb;
    float v = in[c];
    float s = v*v;
#pragma unroll
    for (int o = 16; o > 0; o >>= 1) s += __shfl_xor_sync(0xffffffffu, s, o);
    __shared__ float ws[8];
    if ((c & 31) == 0) ws[c >> 5] = s;
    __syncthreads();
    float tot = 0.0f;
#pragma unroll
    for (int i = 0; i < 8; i++) tot += ws[i];
    float rs = rsqrtf(tot / (float)DM + 1e-5f);
    float o = v * rs * w[c];
    __nv_bfloat16 h, l; split_bf16(o, &h, &l);
    uh[(size_t)m*DM + c] = h; ul[(size_t)m*DM + c] = l;
}

// ---------------- conv + dt: 8 tokens per block, rolling register window ----------------
#define TC 8
__global__ void __launch_bounds__(CONVDIM, 2)
k_convdt2(const float* __restrict__ zx,
          const float* __restrict__ cwf, const float* __restrict__ cbf,
          const float* __restrict__ dtbf,
          const float* __restrict__ cwb, const float* __restrict__ cbb,
          const float* __restrict__ dtbb,
          float* __restrict__ X, float* __restrict__ Bo, float* __restrict__ Co,
          float* __restrict__ dto) {
    int m0 = blockIdx.x * TC;
    int c = threadIdx.x;
    int t0;
    const float *cw, *cb, *dtb;
    if (m0 < MFWD) { t0 = m0 & (TFWD-1); cw = cwf; cb = cbf; dtb = dtbf; }
    else           { t0 = (m0 - MFWD) & (TBWD-1); cw = cwb; cb = cbb; dtb = dtbb; }
    float w0 = cw[c*4], w1 = cw[c*4+1], w2 = cw[c*4+2], w3 = cw[c*4+3];
    float bi = cb[c];
    float win[TC+3];
#pragma unroll
    for (int i = 0; i < TC+3; i++) {
        int tt = t0 - 3 + i;
        win[i] = (tt >= 0) ? zx[((size_t)(m0 - 3 + i))*DPROJ + DIN + c] : 0.0f;
    }
#pragma unroll
    for (int j = 0; j < TC; j++) {
        float acc = bi + win[j]*w0 + win[j+1]*w1 + win[j+2]*w2 + win[j+3]*w3;
        float v = silu_f(acc);
        int m = m0 + j;
        if (c < DIN)             X[(size_t)m*DIN + c] = v;
        else if (c < DIN+DSTATE) Bo[m*DSTATE + (c-DIN)] = v;
        else                     Co[m*DSTATE + (c-DIN-DSTATE)] = v;
    }
    if (c < NH) {
        float db = dtb[c];
#pragma unroll
        for (int j = 0; j < TC; j++) {
            int m = m0 + j;
            dto[m*NH + c] = softplus_f(zx[(size_t)m*DPROJ + 2*DIN + 2*DSTATE + c] + db);
        }
    }
}

// ---------------- scan v5 (proven R13): depth-4 register prefetch pipeline ----------------
__global__ void __launch_bounds__(512)
k_scan5(const float* __restrict__ X, const float* __restrict__ Bb, const float* __restrict__ Cb,
        const float* __restrict__ dtb,
        const float* __restrict__ Alogf, const float* __restrict__ Dpf,
        const float* __restrict__ Alogb, const float* __restrict__ Dpb) {
    float* __restrict__ Y = g_y;
    int blk = blockIdx.x;
    int T, rowbase, h;
    float A, Dh;
    if (blk < 64) {
        int b = blk >> 3; h = blk & 7;
        T = TFWD; rowbase = b * TFWD;
        A = -expf(Alogf[h]); Dh = Dpf[h];
    } else {
        int b = (blk - 64) >> 3; h = blk & 7;
        T = TBWD; rowbase = MFWD + b * TBWD;
        A = -expf(Alogb[h]); Dh = Dpb[h];
    }
    int wid = threadIdx.x >> 5, lane = threadIdx.x & 31;
    int pg = lane >> 3, ng = lane & 7;
    int p = wid*4 + pg;
    const float4* B4 = reinterpret_cast<const float4*>(Bb);
    const float4* C4 = reinterpret_cast<const float4*>(Cb);

    float4 Brb[4], Crb[4];
    float dtrb[4], xrb[4];
#pragma unroll
    for (int j = 0; j < 4; j++) {
        int rr = rowbase + j;
        Brb[j]  = B4[(size_t)rr*8 + ng];
        Crb[j]  = C4[(size_t)rr*8 + ng];
        dtrb[j] = dtb[(size_t)rr*NH + h];
        xrb[j]  = X[(size_t)rr*DIN + h*HD + p];
    }

    float s0 = 0.f, s1 = 0.f, s2 = 0.f, s3 = 0.f;
    for (int t = 0; t < T; t += 4) {
#pragma unroll
        for (int j = 0; j < 4; j++) {
            int tt = t + j;
            float4 Bv = Brb[j], Cv = Crb[j];
            float dtc = dtrb[j], xc = xrb[j];
            int rn = rowbase + (((tt+4) < T) ? (tt+4) : (T-1));
            Brb[j]  = B4[(size_t)rn*8 + ng];
            Crb[j]  = C4[(size_t)rn*8 + ng];
            dtrb[j] = dtb[(size_t)rn*NH + h];
            xrb[j]  = X[(size_t)rn*DIN + h*HD + p];
            float dA = expf(dtc * A);
            float dx = dtc * xc;
            s0 = s0*dA + dx*Bv.x;
            s1 = s1*dA + dx*Bv.y;
            s2 = s2*dA + dx*Bv.z;
            s3 = s3*dA + dx*Bv.w;
            float y = s0*Cv.x + s1*Cv.y + s2*Cv.z + s3*Cv.w;
            y += __shfl_xor_sync(0xffffffffu, y, 1);
            y += __shfl_xor_sync(0xffffffffu, y, 2);
            y += __shfl_xor_sync(0xffffffffu, y, 4);
            if (ng == 0) Y[(size_t)(rowbase + tt)*DIN + h*HD + p] = y + Dh*xc;
        }
    }
}

// ---------------- combined gated rmsnorm -> bf16 hi/lo ----------------
__global__ void k_gatednorm2(const float* __restrict__ Y, const float* __restrict__ zx,
                             const float* __restrict__ gwf, const float* __restrict__ gwb,
                             __nv_bfloat16* __restrict__ uh, __nv_bfloat16* __restrict__ ul) {
    int m = blockIdx.x;
    int c = threadIdx.x; // 512
    const float* gw = (m < MFWD) ? gwf : gwb;
    float z = zx[(size_t)m*DPROJ + c];
    float g = Y[(size_t)m*DIN + c] * silu_f(z);
    float s = g*g;
#pragma unroll
    for (int o = 16; o > 0; o >>= 1) s += __shfl_xor_sync(0xffffffffu, s, o);
    __shared__ float ws[16];
    if ((c & 31) == 0) ws[c >> 5] = s;
    __syncthreads();
    float tot = 0.0f;
#pragma unroll
    for (int i = 0; i < 16; i++) tot += ws[i];
    float rs = rsqrtf(tot / (float)DIN + 1e-5f);
    float o = g * rs * gw[c];
    __nv_bfloat16 h, l; split_bf16(o, &h, &l);
    uh[(size_t)m*DIN + c] = h; ul[(size_t)m*DIN + c] = l;
}

// ---------------- concat + split for final GEMM ----------------
__global__ void k_catsplit(const float* __restrict__ hf, const float* __restrict__ hb,
                           __nv_bfloat16* __restrict__ uh, __nv_bfloat16* __restrict__ ul) {
    int idx = blockIdx.x * 256 + threadIdx.x;
    int m = idx >> 9, c = idx & 511;
    int b = m >> 7, jj = m & 127;
    float v = (c < 256) ? hf[((size_t)b*NTOK + NMASK + jj)*DM + c]
                        : hb[((size_t)b*TBWD + (127 - jj))*DM + (c - 256)];
    __nv_bfloat16 h, l; split_bf16(v, &h, &l);
    uh[idx] = h; ul[idx] = l;
}

// ================= host =================
extern "C" void kernel_launch(void* const* d_in, const int* in_sizes, int n_in,
                              void* d_out, int out_size) {
    float *aux, *pp, *hf, *hb, *zx, *X, *Bbuf, *Cbuf, *dt, *Y;
    __nv_bfloat16 *pch, *pcl, *uh, *ul, *u2h, *u2l, *wph, *wpl, *wih, *wil, *woh, *wol, *wfh, *wfl;
    cudaGetSymbolAddress((void**)&aux, g_aux);
    cudaGetSymbolAddress((void**)&pp,  g_pp);
    cudaGetSymbolAddress((void**)&hf,  g_hf);
    cudaGetSymbolAddress((void**)&hb,  g_hb);
    cudaGetSymbolAddress((void**)&zx,  g_zx);
    cudaGetSymbolAddress((void**)&X,   g_x);
    cudaGetSymbolAddress((void**)&Bbuf, g_Bb);
    cudaGetSymbolAddress((void**)&Cbuf, g_Cb);
    cudaGetSymbolAddress((void**)&dt,  g_dt);
    cudaGetSymbolAddress((void**)&Y,   g_y);
    cudaGetSymbolAddress((void**)&pch, g_pch);
    cudaGetSymbolAddress((void**)&pcl, g_pcl);
    cudaGetSymbolAddress((void**)&uh,  g_uh);
    cudaGetSymbolAddress((void**)&ul,  g_ul);
    cudaGetSymbolAddress((void**)&u2h, g_u2h);
    cudaGetSymbolAddress((void**)&u2l, g_u2l);
    cudaGetSymbolAddress((void**)&wph, g_wph);
    cudaGetSymbolAddress((void**)&wpl, g_wpl);
    cudaGetSymbolAddress((void**)&wih, g_wih);
    cudaGetSymbolAddress((void**)&wil, g_wil);
    cudaGetSymbolAddress((void**)&woh, g_woh);
    cudaGetSymbolAddress((void**)&wol, g_wol);
    cudaGetSymbolAddress((void**)&wfh, g_wfh);
    cudaGetSymbolAddress((void**)&wfl, g_wfl);

    const float* x_prefix   = (const float*)d_in[0];
    const float* y_aux      = (const float*)d_in[1];
    const float* pre_conv_w = (const float*)d_in[2];
    const float* pre_conv_b = (const float*)d_in[3];
    const float* patch_w    = (const float*)d_in[4];
    const float* patch_b    = (const float*)d_in[5];
    const float* mask_token = (const float*)d_in[6];
    const float* aux_w      = (const float*)d_in[7];
    const float* aux_b      = (const float*)d_in[8];

    const float *patch_out_w, *patch_out_b;
    int fbase, bbase;
    if (n_in > 9 && in_sizes[9] == 65536) {
        patch_out_w = (const float*)d_in[9];
        patch_out_b = (const float*)d_in[10];
        fbase = 11; bbase = 20;
    } else {
        fbase = 9; bbase = 18;
        patch_out_w = (const float*)d_in[27];
        patch_out_b = (const float*)d_in[28];
    }
    const float* fW[9]; const float* bW[9];
    for (int i = 0; i < 9; i++) { fW[i] = (const float*)d_in[fbase+i]; bW[i] = (const float*)d_in[bbase+i]; }

    cudaFuncSetAttribute(k_mmagemm512<0>, cudaFuncAttributeMaxDynamicSharedMemorySize, 2*BUF2_SZ);
    cudaFuncSetAttribute(k_mmagemm512<1>, cudaFuncAttributeMaxDynamicSharedMemorySize, 2*BUF2_SZ);
    cudaFuncSetAttribute(k_mmagemm64<0>, cudaFuncAttributeMaxDynamicSharedMemorySize, 2*BUF_SZ);
    cudaFuncSetAttribute(k_mmagemm64<1>, cudaFuncAttributeMaxDynamicSharedMemorySize, 2*BUF_SZ);

    // launch order: patch GEMM in profiled slot 4
    k_aux<<<1, 256>>>(y_aux, aux_w, aux_b, aux);                               // 1
    k_cvt_all<<<dim3((NPADI*DM)/256, 1, 13), 256>>>(fW[1], bW[1], fW[8], bW[8], // 2
        patch_out_w, patch_w, wih, wil, woh, wol, wfh, wfl, wph, wpl);
    k_preconv<<<MPATCH, 256>>>(x_prefix, pre_conv_w, pre_conv_b, pch, pcl);    // 3
    k_mmagemm512<0><<<dim3(DM/128, MPATCH/128, KSPLIT), 512, 2*BUF2_SZ>>>(     // 4 (profiled)
        pch, pcl, wph, wpl, wph, wpl, pp, KCHUNK, KPATCH, DM, DM);
    k_patchfix<<<(MPATCH*DM)/256, 256>>>(pp, patch_b, aux, mask_token, hf, hb);

    for (int lay = 0; lay < 2; lay++) {
        k_rmsnorm2<<<MTOT, DM>>>(hf, hb, fW[0] + lay*DM, bW[0] + lay*DM, uh, ul);
        k_mmagemm512<1><<<dim3(NPADI/128, MTOT/128, 1), 512, 2*BUF2_SZ>>>(
            uh, ul,
            wih + (size_t)lay*NPADI*DM,     wil + (size_t)lay*NPADI*DM,
            wih + (size_t)(2+lay)*NPADI*DM, wil + (size_t)(2+lay)*NPADI*DM,
            zx, DM, DM, DPROJ, DPROJ);
        k_convdt2<<<MTOT/TC, CONVDIM>>>(zx,
            fW[2] + lay*CONVDIM*4, fW[3] + lay*CONVDIM, fW[4] + lay*NH,
            bW[2] + lay*CONVDIM*4, bW[3] + lay*CONVDIM, bW[4] + lay*NH,
            X, Bbuf, Cbuf, dt);
        k_scan5<<<128, 512>>>(X, Bbuf, Cbuf, dt,
            fW[5] + lay*NH, fW[6] + lay*NH, bW[5] + lay*NH, bW[6] + lay*NH);
        k_gatednorm2<<<MTOT, DIN>>>(Y, zx, fW[7] + lay*DIN, bW[7] + lay*DIN, u2h, u2l);
        k_mmagemm64<0><<<dim3(DM/64, MTOT/128), 256, 2*BUF_SZ>>>(
            u2h, u2l,
            woh + (size_t)lay*DM*DIN,     wol + (size_t)lay*DM*DIN,
            woh + (size_t)(2+lay)*DM*DIN, wol + (size_t)(2+lay)*DM*DIN,
            hf, hb, nullptr, DIN);
    }

    // final: concat+split, then 1024x128 GEMM (K=512) straight into d_out
    k_catsplit<<<(1024*512)/256, 256>>>(hf, hb, u2h, u2l);
    k_mmagemm64<1><<<dim3(2, 8), 256, 2*BUF_SZ>>>(
        u2h, u2l, wfh, wfl, wfh, wfl, (float*)d_out, nullptr, patch_out_b, 2*DM);

    (void)in_sizes; (void)n_in; (void)out_size;
}

// round 17
// speedup vs baseline: 1.6070x; 1.0274x over previous
#include <cuda_runtime.h>
#include <cuda_bf16.h>
#include <math.h>
#include <stdint.h>

// ---------------- problem constants ----------------
#define BB 8
#define TPRE 6144
#define CIN 8
#define OUTLEN 2048
#define OUTC 8
#define AUXD 16
#define DM 256
#define DSTATE 32
#define HD 64
#define DIN 512
#define NH 8
#define CONVDIM 576
#define DPROJ 1096
#define NPADI 1152
#define PATCHN 16
#define NTOK 512
#define NMASK 384
#define TFWD 512
#define TBWD 128
#define MFWD (BB*TFWD)    // 4096
#define MBWD (BB*TBWD)    // 1024
#define MTOT (MFWD+MBWD)  // 5120
#define MPATCH (BB*NMASK) // 3072
#define KPATCH 4096
#define KSPLIT 4
#define KCHUNK 1024

// ---------------- scratch ----------------
__device__ __align__(256) float g_aux[BB*DM];
__device__ __align__(256) float g_pp[(size_t)KSPLIT*MPATCH*DM];
__device__ __align__(256) float g_hf[(size_t)BB*NTOK*DM];
__device__ __align__(256) float g_hb[(size_t)BB*TBWD*DM];
__device__ __align__(256) float g_zx[(size_t)MTOT*DPROJ];
__device__ __align__(256) float g_x [(size_t)MTOT*DIN];
__device__ __align__(256) float g_Bb[(size_t)MTOT*DSTATE];
__device__ __align__(256) float g_Cb[(size_t)MTOT*DSTATE];
__device__ __align__(256) float g_dt[(size_t)MTOT*NH];
__device__ __align__(256) float g_y [(size_t)MTOT*DIN];

__device__ __align__(256) __nv_bfloat16 g_pch[(size_t)MPATCH*KPATCH];
__device__ __align__(256) __nv_bfloat16 g_pcl[(size_t)MPATCH*KPATCH];
__device__ __align__(256) __nv_bfloat16 g_uh[(size_t)MTOT*DM];
__device__ __align__(256) __nv_bfloat16 g_ul[(size_t)MTOT*DM];
__device__ __align__(256) __nv_bfloat16 g_u2h[(size_t)MTOT*DIN];
__device__ __align__(256) __nv_bfloat16 g_u2l[(size_t)MTOT*DIN];
__device__ __align__(256) __nv_bfloat16 g_wph[(size_t)DM*KPATCH];
__device__ __align__(256) __nv_bfloat16 g_wpl[(size_t)DM*KPATCH];
__device__ __align__(256) __nv_bfloat16 g_wih[(size_t)4*NPADI*DM];
__device__ __align__(256) __nv_bfloat16 g_wil[(size_t)4*NPADI*DM];
__device__ __align__(256) __nv_bfloat16 g_woh[(size_t)4*DM*DIN];
__device__ __align__(256) __nv_bfloat16 g_wol[(size_t)4*DM*DIN];
__device__ __align__(256) __nv_bfloat16 g_wfh[(size_t)128*2*DM];
__device__ __align__(256) __nv_bfloat16 g_wfl[(size_t)128*2*DM];

__device__ __forceinline__ float silu_f(float v) { return v / (1.0f + expf(-v)); }
__device__ __forceinline__ float softplus_f(float v) { return (v > 20.0f) ? v : log1pf(expf(v)); }

__device__ __forceinline__ void split_bf16(float a, __nv_bfloat16* h, __nv_bfloat16* l) {
    __nv_bfloat16 hh = __float2bfloat16_rn(a);
    *h = hh;
    *l = __float2bfloat16_rn(a - __bfloat162float(hh));
}

// ---------------- baseline-PTX helpers ----------------
__device__ __forceinline__ uint32_t smem_u32(const void* p) {
    uint32_t a;
    asm("{ .reg .u64 t; cvta.to.shared.u64 t, %1; cvt.u32.u64 %0, t; }" : "=r"(a) : "l"(p));
    return a;
}
__device__ __forceinline__ void cp_async16(uint32_t dst, const void* src) {
    asm volatile("cp.async.cg.shared.global [%0], [%1], 16;" :: "r"(dst), "l"(src));
}
#define CP_COMMIT() asm volatile("cp.async.commit_group;" ::: "memory")
#define CP_WAIT0()  asm volatile("cp.async.wait_group 0;" ::: "memory")

__device__ __forceinline__ void ldsm_x4(uint32_t* r, uint32_t addr) {
    asm volatile("ldmatrix.sync.aligned.m8n8.x4.shared.b16 {%0,%1,%2,%3}, [%4];"
                 : "=r"(r[0]), "=r"(r[1]), "=r"(r[2]), "=r"(r[3]) : "r"(addr));
}
__device__ __forceinline__ void mma_bf16(float* d, const uint32_t* a, uint32_t b0, uint32_t b1) {
    asm volatile("mma.sync.aligned.m16n8k16.row.col.f32.bf16.bf16.f32 "
        "{%0,%1,%2,%3}, {%4,%5,%6,%7}, {%8,%9}, {%0,%1,%2,%3};"
        : "+f"(d[0]), "+f"(d[1]), "+f"(d[2]), "+f"(d[3])
        : "r"(a[0]), "r"(a[1]), "r"(a[2]), "r"(a[3]), "r"(b0), "r"(b1));
}

#define PADB 80

// ---------------- aux bias ----------------
__global__ void k_aux(const float* __restrict__ y_aux, const float* __restrict__ aux_w,
                      const float* __restrict__ aux_b, float* __restrict__ out) {
    __shared__ float ys[BB*AUXD];
    int c = threadIdx.x;
    if (c < BB*AUXD) ys[c] = y_aux[c];
    __syncthreads();
    float wcol[AUXD];
#pragma unroll
    for (int i = 0; i < AUXD; i++) wcol[i] = aux_w[i*DM + c];
    float bias = aux_b[c];
    for (int b = 0; b < BB; b++) {
        float acc = bias;
#pragma unroll
        for (int i = 0; i < AUXD; i++) acc += ys[b*AUXD + i] * wcol[i];
        out[b*DM + c] = silu_f(acc);
    }
}

// ---------------- pre-conv -> bf16 hi/lo ----------------
__global__ void k_preconv(const float* __restrict__ xp, const float* __restrict__ w,
                          const float* __restrict__ bias,
                          __nv_bfloat16* __restrict__ ph, __nv_bfloat16* __restrict__ pl) {
    int m = blockIdx.x;
    int b = m / NMASK, j = m % NMASK;
    int t0 = j * PATCHN;
    __shared__ float xs[20][CIN];
    int tid = threadIdx.x;
    if (tid < 20*CIN) {
        int tt = t0 - 2 + tid / CIN;
        int i = tid % CIN;
        xs[tid/CIN][i] = (tt >= 0 && tt < TPRE) ? xp[((size_t)b*TPRE + tt)*CIN + i] : 0.0f;
    }
    __syncthreads();
    int c = tid;
    float wr[CIN*5];
#pragma unroll
    for (int q = 0; q < CIN*5; q++) wr[q] = w[c*CIN*5 + q];
    float bi = bias[c];
    size_t ob = (size_t)m*KPATCH + c*PATCHN;
#pragma unroll
    for (int k = 0; k < PATCHN; k++) {
        float acc = bi;
#pragma unroll
        for (int i = 0; i < CIN; i++)
#pragma unroll
            for (int q = 0; q < 5; q++)
                acc += xs[k+q][i] * wr[i*5 + q];
        float v = silu_f(acc);
        __nv_bfloat16 h, l; split_bf16(v, &h, &l);
        ph[ob + k] = h; pl[ob + k] = l;
    }
}

// ---------------- merged weight conversions ----------------
// z 0..3 inproj slots (transpose); z 4..7 outproj (transpose); z 8 final (transpose);
// z 9..12 patch_w (plain copy+split, quarter each)
__global__ void k_cvt_all(const float* __restrict__ fWi, const float* __restrict__ bWi,
                          const float* __restrict__ fWo, const float* __restrict__ bWo,
                          const float* __restrict__ pow_, const float* __restrict__ patchw,
                          __nv_bfloat16* __restrict__ wih, __nv_bfloat16* __restrict__ wil,
                          __nv_bfloat16* __restrict__ woh, __nv_bfloat16* __restrict__ wol,
                          __nv_bfloat16* __restrict__ wfh, __nv_bfloat16* __restrict__ wfl,
                          __nv_bfloat16* __restrict__ wph, __nv_bfloat16* __restrict__ wpl) {
    int z = blockIdx.z;
    int i = blockIdx.x * 256 + threadIdx.x;
    if (z >= 9) {
        size_t off = (size_t)(z - 9) * (DM*KPATCH/4);
        if (i >= DM*KPATCH/4) return;
        float a = patchw[off + i];
        __nv_bfloat16 h, l; split_bf16(a, &h, &l);
        wph[off + i] = h; wpl[off + i] = l;
        return;
    }
    const float* src; int K, N, Npad; __nv_bfloat16 *dh, *dl;
    if (z < 4) {
        src = ((z >> 1) ? bWi : fWi) + (size_t)(z & 1)*DM*DPROJ;
        K = DM; N = DPROJ; Npad = NPADI;
        dh = wih + (size_t)z*NPADI*DM; dl = wil + (size_t)z*NPADI*DM;
    } else if (z < 8) {
        int s = z - 4;
        src = ((s >> 1) ? bWo : fWo) + (size_t)(s & 1)*DIN*DM;
        K = DIN; N = DM; Npad = DM;
        dh = woh + (size_t)s*DM*DIN; dl = wol + (size_t)s*DM*DIN;
    } else {
        src = pow_; K = 2*DM; N = 128; Npad = 128; dh = wfh; dl = wfl;
    }
    if (i >= Npad*K) return;
    int n = i / K, k = i % K;
    float a = (n < N) ? src[(size_t)k*N + n] : 0.0f;
    __nv_bfloat16 h, l; split_bf16(a, &h, &l);
    dh[i] = h; dl[i] = l;
}

// ================= GEMM v2 (proven): 128x128 tile, 512 threads, BK=32 =================
#define B2_OFF_AL 10240
#define B2_OFF_BH 20480
#define B2_OFF_BL 30720
#define BUF2_SZ   40960

template<int MODE>
__global__ void __launch_bounds__(512, 1)
k_mmagemm512(const __nv_bfloat16* __restrict__ Ah, const __nv_bfloat16* __restrict__ Al,
             const __nv_bfloat16* __restrict__ Bh, const __nv_bfloat16* __restrict__ Bl,
             const __nv_bfloat16* __restrict__ B2h, const __nv_bfloat16* __restrict__ B2l,
             float* __restrict__ Cf, int Kchunk, int Kfull, int Nact, int Nstride) {
    extern __shared__ char smem[];
    uint32_t sbase = smem_u32(smem);
    int tid = threadIdx.x;
    int wid = tid >> 5, lane = tid & 31;
    int wm = wid >> 2, wn = wid & 3;
    int m0 = blockIdx.y * 128, n0 = blockIdx.x * 128;
    int kbase = blockIdx.z * Kchunk;
    int NC = Kchunk >> 5;

    const __nv_bfloat16* bh = (MODE == 1 && m0 >= MFWD) ? B2h : Bh;
    const __nv_bfloat16* bl = (MODE == 1 && m0 >= MFWD) ? B2l : Bl;

    float acc[2][4][4];
#pragma unroll
    for (int i = 0; i < 2; i++)
#pragma unroll
        for (int j = 0; j < 4; j++)
#pragma unroll
            for (int q = 0; q < 4; q++) acc[i][j][q] = 0.0f;

    int lrow = tid >> 2, lc16 = tid & 3;
    auto issue = [&](int c) {
        int kb = kbase + c*32;
        uint32_t sb = sbase + (c & 1)*BUF2_SZ;
        uint32_t d = sb + lrow*PADB + lc16*16;
        size_t go = (size_t)lrow*Kfull + kb + lc16*8;
        cp_async16(d,             Ah + (size_t)m0*Kfull + go);
        cp_async16(d + B2_OFF_AL, Al + (size_t)m0*Kfull + go);
        uint32_t db = sb + B2_OFF_BH + lrow*PADB + lc16*16;
        cp_async16(db,                           bh + (size_t)n0*Kfull + go);
        cp_async16(db + (B2_OFF_BL - B2_OFF_BH), bl + (size_t)n0*Kfull + go);
        CP_COMMIT();
    };

    issue(0);
    int mrow = lane & 15;
    int mcol16 = (lane >> 4) * 16;

    for (int c = 0; c < NC; c++) {
        CP_WAIT0();
        __syncthreads();
        if (c + 1 < NC) issue(c + 1);
        uint32_t sb = sbase + (c & 1)*BUF2_SZ;
#pragma unroll
        for (int ks = 0; ks < 2; ks++) {
            uint32_t ah[2][4], al[2][4], bhf[2][4], blf[2][4];
#pragma unroll
            for (int tm = 0; tm < 2; tm++) {
                uint32_t aaddr = sb + (wm*32 + tm*16 + mrow)*PADB + ks*32 + mcol16;
                ldsm_x4(ah[tm], aaddr);
                ldsm_x4(al[tm], aaddr + B2_OFF_AL);
            }
#pragma unroll
            for (int tn = 0; tn < 2; tn++) {
                uint32_t baddr = sb + B2_OFF_BH + (wn*32 + tn*16 + mrow)*PADB + ks*32 + mcol16;
                ldsm_x4(bhf[tn], baddr);
                ldsm_x4(blf[tn], baddr + (B2_OFF_BL - B2_OFF_BH));
            }
#pragma unroll
            for (int tm = 0; tm < 2; tm++)
#pragma unroll
                for (int tn = 0; tn < 2; tn++)
#pragma unroll
                    for (int h = 0; h < 2; h++) {
                        int j = tn*2 + h;
                        mma_bf16(acc[tm][j], ah[tm], bhf[tn][h], bhf[tn][h+2]);
                        mma_bf16(acc[tm][j], ah[tm], blf[tn][h], blf[tn][h+2]);
                        mma_bf16(acc[tm][j], al[tm], bhf[tn][h], bhf[tn][h+2]);
                    }
        }
    }

    int lr = lane >> 2;
    int lc2 = (lane & 3) * 2;
#pragma unroll
    for (int tm = 0; tm < 2; tm++) {
        int row0 = m0 + wm*32 + tm*16 + lr;
#pragma unroll
        for (int j = 0; j < 4; j++) {
            int n = n0 + wn*32 + j*8 + lc2;
            if (MODE == 0) {
                float* Cp = Cf + (size_t)blockIdx.z * MPATCH * DM;
                *reinterpret_cast<float2*>(Cp + (size_t)row0*DM + n) =
                    make_float2(acc[tm][j][0], acc[tm][j][1]);
                *reinterpret_cast<float2*>(Cp + (size_t)(row0+8)*DM + n) =
                    make_float2(acc[tm][j][2], acc[tm][j][3]);
            } else {
                if (n < Nact) {
                    *reinterpret_cast<float2*>(Cf + (size_t)row0*Nstride + n) =
                        make_float2(acc[tm][j][0], acc[tm][j][1]);
                    *reinterpret_cast<float2*>(Cf + (size_t)(row0+8)*Nstride + n) =
                        make_float2(acc[tm][j][2], acc[tm][j][3]);
                }
            }
        }
    }
}

// ================= GEMM v1 (proven): 128x64 tile, 256 threads =================
// MODE 0: outproj residual +=, split hf/hb. MODE 1: final +bias -> out.
#define OFF_AL 10240
#define OFF_BH 20480
#define OFF_BL 25600
#define BUF_SZ 30720

template<int MODE>
__global__ void __launch_bounds__(256, 2)
k_mmagemm64(const __nv_bfloat16* __restrict__ Ah, const __nv_bfloat16* __restrict__ Al,
            const __nv_bfloat16* __restrict__ Bh, const __nv_bfloat16* __restrict__ Bl,
            const __nv_bfloat16* __restrict__ B2h, const __nv_bfloat16* __restrict__ B2l,
            float* __restrict__ Cf, float* __restrict__ Cb,
            const float* __restrict__ bias, int Kfull) {
    extern __shared__ char smem[];
    uint32_t sbase = smem_u32(smem);
    int tid = threadIdx.x;
    int wid = tid >> 5, lane = tid & 31;
    int wm = wid >> 1, wn = wid & 1;
    int m0 = blockIdx.y * 128, n0 = blockIdx.x * 64;
    int NC = Kfull >> 5;

    const __nv_bfloat16* bh = (MODE == 0 && m0 >= MFWD) ? B2h : Bh;
    const __nv_bfloat16* bl = (MODE == 0 && m0 >= MFWD) ? B2l : Bl;

    float acc[2][4][4];
#pragma unroll
    for (int i = 0; i < 2; i++)
#pragma unroll
        for (int j = 0; j < 4; j++)
#pragma unroll
            for (int q = 0; q < 4; q++) acc[i][j][q] = 0.0f;

    auto issue = [&](int c) {
        int kb = c*32;
        uint32_t sb = sbase + (c & 1)*BUF_SZ;
#pragma unroll
        for (int it = 0; it < 2; it++) {
            int sg = it*256 + tid;
            int row = sg >> 2, c16 = sg & 3;
            uint32_t d = sb + row*PADB + c16*16;
            cp_async16(d,          Ah + (size_t)(m0 + row)*Kfull + kb + c16*8);
            cp_async16(d + OFF_AL, Al + (size_t)(m0 + row)*Kfull + kb + c16*8);
        }
        {
            int row = tid >> 2, c16 = tid & 3;
            uint32_t d = sb + OFF_BH + row*PADB + c16*16;
            cp_async16(d, bh + (size_t)(n0 + row)*Kfull + kb + c16*8);
            cp_async16(d + (OFF_BL - OFF_BH), bl + (size_t)(n0 + row)*Kfull + kb + c16*8);
        }
        CP_COMMIT();
    };

    issue(0);
    int lrow = lane & 15;
    int lcol16 = (lane >> 4) * 16;

    for (int c = 0; c < NC; c++) {
        CP_WAIT0();
        __syncthreads();
        if (c + 1 < NC) issue(c + 1);
        uint32_t sb = sbase + (c & 1)*BUF_SZ;
#pragma unroll
        for (int ks = 0; ks < 2; ks++) {
            uint32_t ah[2][4], al[2][4], bhf[2][4], blf[2][4];
#pragma unroll
            for (int tm = 0; tm < 2; tm++) {
                uint32_t aaddr = sb + (wm*32 + tm*16 + lrow)*PADB + ks*32 + lcol16;
                ldsm_x4(ah[tm], aaddr);
                ldsm_x4(al[tm], aaddr + OFF_AL);
            }
#pragma unroll
            for (int tn = 0; tn < 2; tn++) {
                uint32_t baddr = sb + OFF_BH + (wn*32 + tn*16 + lrow)*PADB + ks*32 + lcol16;
                ldsm_x4(bhf[tn], baddr);
                ldsm_x4(blf[tn], baddr + (OFF_BL - OFF_BH));
            }
#pragma unroll
            for (int tm = 0; tm < 2; tm++)
#pragma unroll
                for (int tn = 0; tn < 2; tn++)
#pragma unroll
                    for (int h = 0; h < 2; h++) {
                        int j = tn*2 + h;
                        mma_bf16(acc[tm][j], ah[tm], bhf[tn][h], bhf[tn][h+2]);
                        mma_bf16(acc[tm][j], ah[tm], blf[tn][h], blf[tn][h+2]);
                        mma_bf16(acc[tm][j], al[tm], bhf[tn][h], bhf[tn][h+2]);
                    }
        }
    }

    int lr = lane >> 2;
    int lc2 = (lane & 3) * 2;
#pragma unroll
    for (int tm = 0; tm < 2; tm++) {
        int row0 = m0 + wm*32 + tm*16 + lr;
#pragma unroll
        for (int j = 0; j < 4; j++) {
            int n = n0 + wn*32 + j*8 + lc2;
            if (MODE == 0) {
#pragma unroll
                for (int half = 0; half < 2; half++) {
                    int m = row0 + half*8;
                    float* p = (m < MFWD) ? (Cf + (size_t)m*DM + n)
                                          : (Cb + (size_t)(m - MFWD)*DM + n);
                    float2 r = *reinterpret_cast<float2*>(p);
                    r.x += acc[tm][j][half*2 + 0];
                    r.y += acc[tm][j][half*2 + 1];
                    *reinterpret_cast<float2*>(p) = r;
                }
            } else {
                float b0 = bias[n], b1 = bias[n+1];
                *reinterpret_cast<float2*>(Cf + (size_t)row0*128 + n) =
                    make_float2(acc[tm][j][0] + b0, acc[tm][j][1] + b1);
                *reinterpret_cast<float2*>(Cf + (size_t)(row0+8)*128 + n) =
                    make_float2(acc[tm][j][2] + b0, acc[tm][j][3] + b1);
            }
        }
    }
}

// ---------------- fused: patch split-K reduce + bias + aux + mask fill ----------------
__global__ void k_patchfix(const float* __restrict__ pp, const float* __restrict__ bias,
                           const float* __restrict__ aux, const float* __restrict__ mask_token,
                           float* __restrict__ hf, float* __restrict__ hb) {
    int idx = blockIdx.x * 256 + threadIdx.x;
    int m = idx >> 8, n = idx & 255;
    float v = bias[n];
#pragma unroll
    for (int z = 0; z < KSPLIT; z++) v += pp[(size_t)z*MPATCH*DM + idx];
    int b = m / NMASK, j = m % NMASK;
    hf[((size_t)b*NTOK + j)*DM + n] = v + aux[b*DM + n];
    if (idx < BB*TBWD*DM) {
        int c = idx & 255;
        int jj = (idx >> 8) & 127;
        int bb = idx >> 15;
        float mv = mask_token[c] + aux[bb*DM + c];
        hf[((size_t)bb*NTOK + NMASK + jj)*DM + c] = mv;
        hb[((size_t)bb*TBWD + jj)*DM + c] = mv;
    }
}

// ---------------- combined rmsnorm -> bf16 hi/lo ----------------
__global__ void k_rmsnorm2(const float* __restrict__ hf, const float* __restrict__ hb,
                           const float* __restrict__ wf, const float* __restrict__ wb,
                           __nv_bfloat16* __restrict__ uh, __nv_bfloat16* __restrict__ ul) {
    int m = blockIdx.x;
    int c = threadIdx.x; // 256
    const float* in = (m < MFWD) ? (hf + (size_t)m*DM) : (hb + (size_t)(m-MFWD)*DM);
    const float* w  = (m < MFWD) ? wf : wb;
    float v = in[c];
    float s = v*v;
#pragma unroll
    for (int o = 16; o > 0; o >>= 1) s += __shfl_xor_sync(0xffffffffu, s, o);
    __shared__ float ws[8];
    if ((c & 31) == 0) ws[c >> 5] = s;
    __syncthreads();
    float tot = 0.0f;
#pragma unroll
    for (int i = 0; i < 8; i++) tot += ws[i];
    float rs = rsqrtf(tot / (float)DM + 1e-5f);
    float o = v * rs * w[c];
    __nv_bfloat16 h, l; split_bf16(o, &h, &l);
    uh[(size_t)m*DM + c] = h; ul[(size_t)m*DM + c] = l;
}

// ---------------- conv + dt: 8 tokens per block, rolling register window ----------------
#define TC 8
__global__ void __launch_bounds__(CONVDIM, 2)
k_convdt2(const float* __restrict__ zx,
          const float* __restrict__ cwf, const float* __restrict__ cbf,
          const float* __restrict__ dtbf,
          const float* __restrict__ cwb, const float* __restrict__ cbb,
          const float* __restrict__ dtbb,
          float* __restrict__ X, float* __restrict__ Bo, float* __restrict__ Co,
          float* __restrict__ dto) {
    int m0 = blockIdx.x * TC;
    int c = threadIdx.x;
    int t0;
    const float *cw, *cb, *dtb;
    if (m0 < MFWD) { t0 = m0 & (TFWD-1); cw = cwf; cb = cbf; dtb = dtbf; }
    else           { t0 = (m0 - MFWD) & (TBWD-1); cw = cwb; cb = cbb; dtb = dtbb; }
    float w0 = cw[c*4], w1 = cw[c*4+1], w2 = cw[c*4+2], w3 = cw[c*4+3];
    float bi = cb[c];
    float win[TC+3];
#pragma unroll
    for (int i = 0; i < TC+3; i++) {
        int tt = t0 - 3 + i;
        win[i] = (tt >= 0) ? zx[((size_t)(m0 - 3 + i))*DPROJ + DIN + c] : 0.0f;
    }
#pragma unroll
    for (int j = 0; j < TC; j++) {
        float acc = bi + win[j]*w0 + win[j+1]*w1 + win[j+2]*w2 + win[j+3]*w3;
        float v = silu_f(acc);
        int m = m0 + j;
        if (c < DIN)             X[(size_t)m*DIN + c] = v;
        else if (c < DIN+DSTATE) Bo[m*DSTATE + (c-DIN)] = v;
        else                     Co[m*DSTATE + (c-DIN-DSTATE)] = v;
    }
    if (c < NH) {
        float db = dtb[c];
#pragma unroll
        for (int j = 0; j < TC; j++) {
            int m = m0 + j;
            dto[m*NH + c] = softplus_f(zx[(size_t)m*DPROJ + 2*DIN + 2*DSTATE + c] + db);
        }
    }
}

// ---------------- scan v6: depth-8 register prefetch pipeline ----------------
// Same as proven scan5 but prefetch distance 8 steps (~320 cyc > L2 234) so loads
// are fully covered. T=512 and T=128 both divisible by 8.
__global__ void __launch_bounds__(512)
k_scan6(const float* __restrict__ X, const float* __restrict__ Bb, const float* __restrict__ Cb,
        const float* __restrict__ dtb,
        const float* __restrict__ Alogf, const float* __restrict__ Dpf,
        const float* __restrict__ Alogb, const float* __restrict__ Dpb) {
    float* __restrict__ Y = g_y;
    int blk = blockIdx.x;
    int T, rowbase, h;
    float A, Dh;
    if (blk < 64) {
        int b = blk >> 3; h = blk & 7;
        T = TFWD; rowbase = b * TFWD;
        A = -expf(Alogf[h]); Dh = Dpf[h];
    } else {
        int b = (blk - 64) >> 3; h = blk & 7;
        T = TBWD; rowbase = MFWD + b * TBWD;
        A = -expf(Alogb[h]); Dh = Dpb[h];
    }
    int wid = threadIdx.x >> 5, lane = threadIdx.x & 31;
    int pg = lane >> 3, ng = lane & 7;
    int p = wid*4 + pg;
    const float4* B4 = reinterpret_cast<const float4*>(Bb);
    const float4* C4 = reinterpret_cast<const float4*>(Cb);

    float4 Brb[8], Crb[8];
    float dtrb[8], xrb[8];
#pragma unroll
    for (int j = 0; j < 8; j++) {
        int rr = rowbase + j;
        Brb[j]  = B4[(size_t)rr*8 + ng];
        Crb[j]  = C4[(size_t)rr*8 + ng];
        dtrb[j] = dtb[(size_t)rr*NH + h];
        xrb[j]  = X[(size_t)rr*DIN + h*HD + p];
    }

    float s0 = 0.f, s1 = 0.f, s2 = 0.f, s3 = 0.f;
    for (int t = 0; t < T; t += 8) {
#pragma unroll
        for (int j = 0; j < 8; j++) {
            int tt = t + j;
            float4 Bv = Brb[j], Cv = Crb[j];
            float dtc = dtrb[j], xc = xrb[j];
            int rn = rowbase + (((tt+8) < T) ? (tt+8) : (T-1));
            Brb[j]  = B4[(size_t)rn*8 + ng];
            Crb[j]  = C4[(size_t)rn*8 + ng];
            dtrb[j] = dtb[(size_t)rn*NH + h];
            xrb[j]  = X[(size_t)rn*DIN + h*HD + p];
            float dA = expf(dtc * A);
            float dx = dtc * xc;
            s0 = s0*dA + dx*Bv.x;
            s1 = s1*dA + dx*Bv.y;
            s2 = s2*dA + dx*Bv.z;
            s3 = s3*dA + dx*Bv.w;
            float y = s0*Cv.x + s1*Cv.y + s2*Cv.z + s3*Cv.w;
            y += __shfl_xor_sync(0xffffffffu, y, 1);
            y += __shfl_xor_sync(0xffffffffu, y, 2);
            y += __shfl_xor_sync(0xffffffffu, y, 4);
            if (ng == 0) Y[(size_t)(rowbase + tt)*DIN + h*HD + p] = y + Dh*xc;
        }
    }
}

// ---------------- combined gated rmsnorm -> bf16 hi/lo ----------------
__global__ void k_gatednorm2(const float* __restrict__ Y, const float* __restrict__ zx,
                             const float* __restrict__ gwf, const float* __restrict__ gwb,
                             __nv_bfloat16* __restrict__ uh, __nv_bfloat16* __restrict__ ul) {
    int m = blockIdx.x;
    int c = threadIdx.x; // 512
    const float* gw = (m < MFWD) ? gwf : gwb;
    float z = zx[(size_t)m*DPROJ + c];
    float g = Y[(size_t)m*DIN + c] * silu_f(z);
    float s = g*g;
#pragma unroll
    for (int o = 16; o > 0; o >>= 1) s += __shfl_xor_sync(0xffffffffu, s, o);
    __shared__ float ws[16];
    if ((c & 31) == 0) ws[c >> 5] = s;
    __syncthreads();
    float tot = 0.0f;
#pragma unroll
    for (int i = 0; i < 16; i++) tot += ws[i];
    float rs = rsqrtf(tot / (float)DIN + 1e-5f);
    float o = g * rs * gw[c];
    __nv_bfloat16 h, l; split_bf16(o, &h, &l);
    uh[(size_t)m*DIN + c] = h; ul[(size_t)m*DIN + c] = l;
}

// ---------------- concat + split for final GEMM ----------------
__global__ void k_catsplit(const float* __restrict__ hf, const float* __restrict__ hb,
                           __nv_bfloat16* __restrict__ uh, __nv_bfloat16* __restrict__ ul) {
    int idx = blockIdx.x * 256 + threadIdx.x;
    int m = idx >> 9, c = idx & 511;
    int b = m >> 7, jj = m & 127;
    float v = (c < 256) ? hf[((size_t)b*NTOK + NMASK + jj)*DM + c]
                        : hb[((size_t)b*TBWD + (127 - jj))*DM + (c - 256)];
    __nv_bfloat16 h, l; split_bf16(v, &h, &l);
    uh[idx] = h; ul[idx] = l;
}

// ================= host =================
extern "C" void kernel_launch(void* const* d_in, const int* in_sizes, int n_in,
                              void* d_out, int out_size) {
    float *aux, *pp, *hf, *hb, *zx, *X, *Bbuf, *Cbuf, *dt, *Y;
    __nv_bfloat16 *pch, *pcl, *uh, *ul, *u2h, *u2l, *wph, *wpl, *wih, *wil, *woh, *wol, *wfh, *wfl;
    cudaGetSymbolAddress((void**)&aux, g_aux);
    cudaGetSymbolAddress((void**)&pp,  g_pp);
    cudaGetSymbolAddress((void**)&hf,  g_hf);
    cudaGetSymbolAddress((void**)&hb,  g_hb);
    cudaGetSymbolAddress((void**)&zx,  g_zx);
    cudaGetSymbolAddress((void**)&X,   g_x);
    cudaGetSymbolAddress((void**)&Bbuf, g_Bb);
    cudaGetSymbolAddress((void**)&Cbuf, g_Cb);
    cudaGetSymbolAddress((void**)&dt,  g_dt);
    cudaGetSymbolAddress((void**)&Y,   g_y);
    cudaGetSymbolAddress((void**)&pch, g_pch);
    cudaGetSymbolAddress((void**)&pcl, g_pcl);
    cudaGetSymbolAddress((void**)&uh,  g_uh);
    cudaGetSymbolAddress((void**)&ul,  g_ul);
    cudaGetSymbolAddress((void**)&u2h, g_u2h);
    cudaGetSymbolAddress((void**)&u2l, g_u2l);
    cudaGetSymbolAddress((void**)&wph, g_wph);
    cudaGetSymbolAddress((void**)&wpl, g_wpl);
    cudaGetSymbolAddress((void**)&wih, g_wih);
    cudaGetSymbolAddress((void**)&wil, g_wil);
    cudaGetSymbolAddress((void**)&woh, g_woh);
    cudaGetSymbolAddress((void**)&wol, g_wol);
    cudaGetSymbolAddress((void**)&wfh, g_wfh);
    cudaGetSymbolAddress((void**)&wfl, g_wfl);

    const float* x_prefix   = (const float*)d_in[0];
    const float* y_aux      = (const float*)d_in[1];
    const float* pre_conv_w = (const float*)d_in[2];
    const float* pre_conv_b = (const float*)d_in[3];
    const float* patch_w    = (const float*)d_in[4];
    const float* patch_b    = (const float*)d_in[5];
    const float* mask_token = (const float*)d_in[6];
    const float* aux_w      = (const float*)d_in[7];
    const float* aux_b      = (const float*)d_in[8];

    const float *patch_out_w, *patch_out_b;
    int fbase, bbase;
    if (n_in > 9 && in_sizes[9] == 65536) {
        patch_out_w = (const float*)d_in[9];
        patch_out_b = (const float*)d_in[10];
        fbase = 11; bbase = 20;
    } else {
        fbase = 9; bbase = 18;
        patch_out_w = (const float*)d_in[27];
        patch_out_b = (const float*)d_in[28];
    }
    const float* fW[9]; const float* bW[9];
    for (int i = 0; i < 9; i++) { fW[i] = (const float*)d_in[fbase+i]; bW[i] = (const float*)d_in[bbase+i]; }

    cudaFuncSetAttribute(k_mmagemm512<0>, cudaFuncAttributeMaxDynamicSharedMemorySize, 2*BUF2_SZ);
    cudaFuncSetAttribute(k_mmagemm512<1>, cudaFuncAttributeMaxDynamicSharedMemorySize, 2*BUF2_SZ);
    cudaFuncSetAttribute(k_mmagemm64<0>, cudaFuncAttributeMaxDynamicSharedMemorySize, 2*BUF_SZ);
    cudaFuncSetAttribute(k_mmagemm64<1>, cudaFuncAttributeMaxDynamicSharedMemorySize, 2*BUF_SZ);

    // launch order: patch GEMM in profiled slot 4
    k_aux<<<1, 256>>>(y_aux, aux_w, aux_b, aux);                               // 1
    k_cvt_all<<<dim3((NPADI*DM)/256, 1, 13), 256>>>(fW[1], bW[1], fW[8], bW[8], // 2
        patch_out_w, patch_w, wih, wil, woh, wol, wfh, wfl, wph, wpl);
    k_preconv<<<MPATCH, 256>>>(x_prefix, pre_conv_w, pre_conv_b, pch, pcl);    // 3
    k_mmagemm512<0><<<dim3(DM/128, MPATCH/128, KSPLIT), 512, 2*BUF2_SZ>>>(     // 4 (profiled)
        pch, pcl, wph, wpl, wph, wpl, pp, KCHUNK, KPATCH, DM, DM);
    k_patchfix<<<(MPATCH*DM)/256, 256>>>(pp, patch_b, aux, mask_token, hf, hb);

    for (int lay = 0; lay < 2; lay++) {
        k_rmsnorm2<<<MTOT, DM>>>(hf, hb, fW[0] + lay*DM, bW[0] + lay*DM, uh, ul);
        k_mmagemm512<1><<<dim3(NPADI/128, MTOT/128, 1), 512, 2*BUF2_SZ>>>(
            uh, ul,
            wih + (size_t)lay*NPADI*DM,     wil + (size_t)lay*NPADI*DM,
            wih + (size_t)(2+lay)*NPADI*DM, wil + (size_t)(2+lay)*NPADI*DM,
            zx, DM, DM, DPROJ, DPROJ);
        k_convdt2<<<MTOT/TC, CONVDIM>>>(zx,
            fW[2] + lay*CONVDIM*4, fW[3] + lay*CONVDIM, fW[4] + lay*NH,
            bW[2] + lay*CONVDIM*4, bW[3] + lay*CONVDIM, bW[4] + lay*NH,
            X, Bbuf, Cbuf, dt);
        k_scan6<<<128, 512>>>(X, Bbuf, Cbuf, dt,
            fW[5] + lay*NH, fW[6] + lay*NH, bW[5] + lay*NH, bW[6] + lay*NH);
        k_gatednorm2<<<MTOT, DIN>>>(Y, zx, fW[7] + lay*DIN, bW[7] + lay*DIN, u2h, u2l);
        k_mmagemm64<0><<<dim3(DM/64, MTOT/128), 256, 2*BUF_SZ>>>(
            u2h, u2l,
            woh + (size_t)lay*DM*DIN,     wol + (size_t)lay*DM*DIN,
            woh + (size_t)(2+lay)*DM*DIN, wol + (size_t)(2+lay)*DM*DIN,
            hf, hb, nullptr, DIN);
    }

    // final: concat+split, then 1024x128 GEMM (K=512) straight into d_out
    k_catsplit<<<(1024*512)/256, 256>>>(hf, hb, u2h, u2l);
    k_mmagemm64<1><<<dim3(2, 8), 256, 2*BUF_SZ>>>(
        u2h, u2l, wfh, wfl, wfh, wfl, (float*)d_out, nullptr, patch_out_b, 2*DM);

    (void)in_sizes; (void)n_in; (void)out_size;
}